// round 11
// baseline (speedup 1.0000x reference)
#include <cuda_runtime.h>
#include <cuda_bf16.h>
#include <cuda_fp16.h>
#include <math.h>
#include <stdint.h>

// ---------------- scratch (static device globals; no runtime alloc) ----------------
__device__ __nv_bfloat16 g_h1_hi[(size_t)512 * 400 * 256];   // conv1 out hi, [b][pos][ci]
__device__ __nv_bfloat16 g_h1_lo[(size_t)512 * 400 * 256];   // conv1 out lo
__device__ float g_h1f[(size_t)512 * 400 * 256];             // conv1 out fp32 (FFMA path)
__device__ __nv_bfloat16 g_w2_hi[81 * 256 * 256];            // pc_w hi, [kk][co][ci]
__device__ __nv_bfloat16 g_w2_lo[81 * 256 * 256];            // pc_w lo
__device__ float g_h2[512 * 9216];                           // conv2 out [b][co*36+s]
__device__ float g_u[512 * 9216];                            // squashed capsules [b][i][k]
__device__ __half g_xhat[(size_t)512 * 10 * 1152 * 16];      // votes [b][o][i][d] (fp16)
__device__ float g_blog0[512 * 10 * 1152];                   // routing logits ping
__device__ float g_blog1[512 * 10 * 1152];                   // routing logits pong
__device__ float g_c[512 * 10 * 1152];                       // softmax coefficients

// ---------------- PTX helpers (sm_80-era; compile on plain sm_103 target) ----------------
__device__ __forceinline__ uint32_t smem_u32(const void* p) {
    uint32_t a;
    asm("{ .reg .u64 t; cvta.to.shared.u64 t, %1; cvt.u32.u64 %0, t; }" : "=r"(a) : "l"(p));
    return a;
}
__device__ __forceinline__ void ldm_x4(uint32_t* r, uint32_t addr) {
    asm volatile("ldmatrix.sync.aligned.m8n8.x4.shared.b16 {%0,%1,%2,%3}, [%4];"
                 : "=r"(r[0]), "=r"(r[1]), "=r"(r[2]), "=r"(r[3]) : "r"(addr));
}
__device__ __forceinline__ void mma_bf16(float* c, const uint32_t* a, const uint32_t* b) {
    asm volatile("mma.sync.aligned.m16n8k16.row.col.f32.bf16.bf16.f32 "
                 "{%0,%1,%2,%3}, {%4,%5,%6,%7}, {%8,%9}, {%0,%1,%2,%3};"
                 : "+f"(c[0]), "+f"(c[1]), "+f"(c[2]), "+f"(c[3])
                 : "r"(a[0]), "r"(a[1]), "r"(a[2]), "r"(a[3]), "r"(b[0]), "r"(b[1]));
}
__device__ __forceinline__ void cp16(uint32_t dst, const void* src) {
    asm volatile("cp.async.cg.shared.global [%0], [%1], 16;" :: "r"(dst), "l"(src));
}
__device__ __forceinline__ void cp_commit() { asm volatile("cp.async.commit_group;" ::: "memory"); }
__device__ __forceinline__ void cp_wait0()  { asm volatile("cp.async.wait_group 0;" ::: "memory"); }
__device__ __forceinline__ void ffma2(unsigned long long& acc,
                                      unsigned long long a,
                                      unsigned long long b) {
    asm("fma.rn.f32x2 %0, %1, %2, %0;" : "+l"(acc) : "l"(a), "l"(b));
}

// ---------------- conv1: [512,1,28,28] -> bf16 hi/lo + fp32, channel-last, ReLU ----------------
__global__ __launch_bounds__(256) void conv1_kernel(const float* __restrict__ x,
                                                    const float* __restrict__ w1,
                                                    const float* __restrict__ b1) {
    __shared__ float xs[784];
    int b  = blockIdx.x;
    int oh0 = blockIdx.y * 10;
    int co = threadIdx.x;
    const float* xb = x + (size_t)b * 784;
    for (int idx = co; idx < 784; idx += 256) xs[idx] = xb[idx];
    __syncthreads();

    float bias = b1[co];
    const float* wco = w1 + co * 81;

    for (int oh = oh0; oh < oh0 + 10; oh++) {
        float acc[20];
#pragma unroll
        for (int ow = 0; ow < 20; ow++) acc[ow] = 0.f;

        for (int kh = 0; kh < 9; kh++) {
            float xr[28];
#pragma unroll
            for (int c = 0; c < 28; c++) xr[c] = xs[(oh + kh) * 28 + c];
#pragma unroll
            for (int kw = 0; kw < 9; kw++) {
                float w = __ldg(&wco[kh * 9 + kw]);
#pragma unroll
                for (int ow = 0; ow < 20; ow++) acc[ow] += w * xr[ow + kw];
            }
        }
        size_t base = (((size_t)b * 400) + oh * 20) * 256 + co;
#pragma unroll
        for (int ow = 0; ow < 20; ow++) {
            float v = acc[ow] + bias;
            v = v > 0.f ? v : 0.f;
            __nv_bfloat16 h = __float2bfloat16(v);
            __nv_bfloat16 l = __float2bfloat16(v - __bfloat162float(h));
            g_h1_hi[base + (size_t)ow * 256] = h;
            g_h1_lo[base + (size_t)ow * 256] = l;
            g_h1f [base + (size_t)ow * 256] = v;
        }
    }
}

// ---------------- pc_w convert (coalesced): [co][ci][k] fp32 -> [kk][co][ci] bf16 hi/lo ----------------
__global__ __launch_bounds__(256) void convert_w2(const float* __restrict__ pcw) {
    extern __shared__ float ws[];    // [ci][81]
    int co = blockIdx.x;
    int t = threadIdx.x;
    const float* src = pcw + (size_t)co * 256 * 81;
    for (int idx = t; idx < 256 * 81; idx += 256) ws[idx] = src[idx];
    __syncthreads();
    int ci = t;
    for (int k = 0; k < 81; k++) {
        float v = ws[ci * 81 + k];
        __nv_bfloat16 h = __float2bfloat16(v);
        __nv_bfloat16 l = __float2bfloat16(v - __bfloat162float(h));
        size_t o = ((size_t)k * 256 + co) * 256 + ci;
        g_w2_hi[o] = h;
        g_w2_lo[o] = l;
    }
}

// ---------------- conv2: hybrid HMMA (192 pos) + FFMA2 (64 pos) per 256-pos tile ----------------
// 12 warps: 0-7 MMA (warp tile 32m x 96n), 8-11 FFMA (thread-per-co, 64 pos in f32x2).
#define LDK 72
#define AHI 0
#define ALO 18432
#define BHI 36864
#define BLO 64512
#define BUFSZ 92160
#define ASF0 184320
#define ASFSZ 16896
#define NITER 324
__global__ __launch_bounds__(384, 1) void conv2_mma(const float* __restrict__ pcb) {
    extern __shared__ char smem[];
    uint32_t sb = smem_u32(smem);
    int tid = threadIdx.x;
    int wid = tid >> 5;
    int lane = tid & 31;
    int mtile = blockIdx.x;      // 0..1   (co block of 128)
    int ntile = blockIdx.y;      // 0..71  (pos block of 256)

    // ======== per-role precompute ========
    // MMA staging (tid < 256)
    int seg = tid & 7;
    int rbase = tid >> 3;
    uint32_t adst[4], aoff[4];
    uint32_t bdst[6], gb[6];
    if (tid < 256) {
#pragma unroll
        for (int j = 0; j < 4; j++) {
            int row = rbase + j * 32;                      // 0..127
            adst[j] = (uint32_t)(row * LDK + seg * 8) * 2;
            aoff[j] = (uint32_t)((mtile * 128 + row) * 256 + seg * 8);
        }
#pragma unroll
        for (int j = 0; j < 6; j++) {
            int row = rbase + j * 32;                      // 0..191
            bdst[j] = (uint32_t)(row * LDK + seg * 8) * 2;
            int p = ntile * 256 + row;
            int b = p / 36;
            int s = p - b * 36;
            int oh = s / 6, ow = s - oh * 6;
            gb[j] = (uint32_t)(((b * 400 + oh * 40 + ow * 2) * 256 + seg * 8));
        }
    }
    // FFMA staging (tid >= 256): thread ft handles pos k, ci quads qstart, qstart+2, ...
    int ft = tid - 256;                                    // 0..127
    uint32_t gbf = 0;
    if (tid >= 256) {
        int k = ft & 63;
        int p = ntile * 256 + 192 + k;
        int b = p / 36;
        int s = p - b * 36;
        int oh = s / 6, ow = s - oh * 6;
        gbf = (uint32_t)((b * 400 + oh * 40 + ow * 2) * 256);
    }

    // accumulators
    float acc[2][12][4];
    unsigned long long facc[32];
    if (tid < 256) {
#pragma unroll
        for (int mt = 0; mt < 2; mt++)
#pragma unroll
            for (int nt = 0; nt < 12; nt++)
#pragma unroll
                for (int j = 0; j < 4; j++) acc[mt][nt][j] = 0.f;
    } else {
#pragma unroll
        for (int j = 0; j < 32; j++) facc[j] = 0ull;
    }

    int wm = wid & 3;
    int wn = wid >> 2;           // 0..1 for MMA warps
    int rowA = lane & 15;
    int kgA  = (lane >> 4) << 3;
    int rowB = ((lane >> 4) << 3) + (lane & 7);
    int kgB  = ((lane >> 3) & 1) << 3;

#define STAGE_MMA(IT, BSEL) do {                                                    \
        int _it = (IT);                                                             \
        int _cb = (_it / 81) << 6;                                                  \
        int _kk = _it - (_it / 81) * 81;                                            \
        int _kh = _kk / 9, _kw = _kk - _kh * 9;                                     \
        uint32_t _bu = sb + (BSEL) * BUFSZ;                                         \
        size_t _abase = ((size_t)_kk * 256) * 256 + _cb;                            \
        uint32_t _boff = (uint32_t)((_kh * 20 + _kw) * 256 + _cb);                  \
        _Pragma("unroll")                                                           \
        for (int j = 0; j < 4; j++) {                                               \
            size_t _s = _abase + aoff[j];                                           \
            cp16(_bu + AHI + adst[j], (const char*)g_w2_hi + _s * 2);               \
            cp16(_bu + ALO + adst[j], (const char*)g_w2_lo + _s * 2);               \
        }                                                                           \
        _Pragma("unroll")                                                           \
        for (int j = 0; j < 6; j++) {                                               \
            size_t _s = (size_t)gb[j] + _boff;                                      \
            cp16(_bu + BHI + bdst[j], (const char*)g_h1_hi + _s * 2);               \
            cp16(_bu + BLO + bdst[j], (const char*)g_h1_lo + _s * 2);               \
        }                                                                           \
    } while (0)

#define STAGE_ASF(IT, BSEL) do {                                                    \
        int _it = (IT);                                                             \
        int _cb = (_it / 81) << 6;                                                  \
        int _kk = _it - (_it / 81) * 81;                                            \
        int _kh = _kk / 9, _kw = _kk - _kh * 9;                                     \
        float* _asf = (float*)(smem + ASF0 + (BSEL) * ASFSZ);                       \
        const float* _src = g_h1f + (size_t)gbf + (_kh * 20 + _kw) * 256 + _cb;     \
        int _k = ft & 63;                                                           \
        _Pragma("unroll")                                                           \
        for (int q = (ft >> 6); q < 16; q += 2) {                                   \
            float4 _v = *(const float4*)(_src + q * 4);                             \
            float* _d = _asf + (q * 4) * 66 + _k;                                   \
            _d[0] = _v.x; _d[66] = _v.y; _d[132] = _v.z; _d[198] = _v.w;            \
        }                                                                           \
    } while (0)

    if (tid < 256) { STAGE_MMA(0, 0); cp_commit(); cp_wait0(); }
    else           { STAGE_ASF(0, 0); }
    __syncthreads();

    for (int it = 0; it < NITER; it++) {
        if (it + 1 < NITER) {
            if (tid < 256) { STAGE_MMA(it + 1, (it + 1) & 1); cp_commit(); }
            else           { STAGE_ASF(it + 1, (it + 1) & 1); }
        }

        uint32_t bu = sb + (it & 1) * BUFSZ;
        if (tid < 256) {
            // -------- MMA path: 192 positions --------
#pragma unroll
            for (int ks = 0; ks < 4; ks++) {
                int k0 = ks * 16;
                uint32_t ahi[2][4], alo[2][4];
#pragma unroll
                for (int mt = 0; mt < 2; mt++) {
                    uint32_t arow = (uint32_t)((wm * 32 + mt * 16 + rowA) * LDK + k0 + kgA) * 2;
                    ldm_x4(ahi[mt], bu + AHI + arow);
                    ldm_x4(alo[mt], bu + ALO + arow);
                }
#pragma unroll
                for (int nh = 0; nh < 3; nh++) {    // 3 chunks of 32 cols = 96 per warp
                    uint32_t bhi[4][2], blo[4][2];
#pragma unroll
                    for (int nq = 0; nq < 2; nq++) {
                        uint32_t brow = (uint32_t)((wn * 96 + nh * 32 + nq * 16 + rowB) * LDK + k0 + kgB) * 2;
                        uint32_t t4[4];
                        ldm_x4(t4, bu + BHI + brow);
                        bhi[2 * nq][0] = t4[0]; bhi[2 * nq][1] = t4[1];
                        bhi[2 * nq + 1][0] = t4[2]; bhi[2 * nq + 1][1] = t4[3];
                        ldm_x4(t4, bu + BLO + brow);
                        blo[2 * nq][0] = t4[0]; blo[2 * nq][1] = t4[1];
                        blo[2 * nq + 1][0] = t4[2]; blo[2 * nq + 1][1] = t4[3];
                    }
#pragma unroll
                    for (int mt = 0; mt < 2; mt++)
#pragma unroll
                        for (int nq = 0; nq < 4; nq++) {
                            int nt = nh * 4 + nq;
                            mma_bf16(acc[mt][nt], ahi[mt], bhi[nq]);
                            mma_bf16(acc[mt][nt], ahi[mt], blo[nq]);
                            mma_bf16(acc[mt][nt], alo[mt], bhi[nq]);
                        }
                }
            }
        } else {
            // -------- FFMA path: 64 positions, fp32 via f32x2 --------
            const __nv_bfloat16* ahi_t = (const __nv_bfloat16*)(smem + (it & 1) * BUFSZ + AHI);
            const __nv_bfloat16* alo_t = (const __nv_bfloat16*)(smem + (it & 1) * BUFSZ + ALO);
            const float* asf = (const float*)(smem + ASF0 + (it & 1) * ASFSZ);
            int co_l = ft;   // local co row 0..127
#pragma unroll 4
            for (int ci = 0; ci < 64; ci++) {
                float w = __bfloat162float(ahi_t[co_l * LDK + ci]) +
                          __bfloat162float(alo_t[co_l * LDK + ci]);
                unsigned long long w2;
                asm("mov.b64 %0, {%1, %1};" : "=l"(w2) : "f"(w));
                const unsigned long long* xrow = (const unsigned long long*)(asf + ci * 66);
#pragma unroll
                for (int j = 0; j < 32; j++) ffma2(facc[j], xrow[j], w2);
            }
        }

        if (it + 1 < NITER && tid < 256) cp_wait0();
        __syncthreads();
    }

    // ======== epilogues ========
    if (tid < 256) {
        int r0 = lane >> 2, cp = lane & 3;
#pragma unroll
        for (int mt = 0; mt < 2; mt++) {
#pragma unroll
            for (int half = 0; half < 2; half++) {
                int m = wm * 32 + mt * 16 + r0 + half * 8;
                int co = mtile * 128 + m;
                float bias = pcb[co];
#pragma unroll
                for (int nt = 0; nt < 12; nt++) {
#pragma unroll
                    for (int e = 0; e < 2; e++) {
                        int p = ntile * 256 + wn * 96 + nt * 8 + 2 * cp + e;
                        int b = p / 36;
                        int s = p - b * 36;
                        g_h2[(size_t)b * 9216 + co * 36 + s] = acc[mt][nt][half * 2 + e] + bias;
                    }
                }
            }
        }
    } else {
        int co = mtile * 128 + ft;
        float bias = pcb[co];
#pragma unroll
        for (int j = 0; j < 32; j++) {
            float lo, hi;
            asm("mov.b64 {%0, %1}, %2;" : "=f"(lo), "=f"(hi) : "l"(facc[j]));
            int p0 = ntile * 256 + 192 + 2 * j;
            int b0 = p0 / 36;
            int s0 = p0 - b0 * 36;
            g_h2[(size_t)b0 * 9216 + co * 36 + s0] = lo + bias;
            int p1 = p0 + 1;
            int b1 = p1 / 36;
            int s1 = p1 - b1 * 36;
            g_h2[(size_t)b1 * 9216 + co * 36 + s1] = hi + bias;
        }
    }
}

// ---------------- squash over 8-dim capsules: g_h2 -> g_u ----------------
__global__ void squash_kernel() {
    int idx = blockIdx.x * 256 + threadIdx.x;
    if (idx >= 512 * 1152) return;
    const float4* p = (const float4*)(g_h2 + (size_t)idx * 8);
    float4 a = p[0], c = p[1];
    float n2 = a.x * a.x + a.y * a.y + a.z * a.z + a.w * a.w +
               c.x * c.x + c.y * c.y + c.z * c.z + c.w * c.w;
    float n = sqrtf(n2);
    float scale = n2 / (1.f + n2) / (n + 1e-8f);
    float4* q = (float4*)(g_u + (size_t)idx * 8);
    a.x *= scale; a.y *= scale; a.z *= scale; a.w *= scale;
    c.x *= scale; c.y *= scale; c.z *= scale; c.w *= scale;
    q[0] = a; q[1] = c;
}

// ---------------- votes, tiled: caps_w tile in smem, 64 b per block; fp16 output ----------------
__global__ __launch_bounds__(256) void xhat_kernel(const float* __restrict__ cw) {
    extern __shared__ float xsm[];
    float* ws = xsm;                    // 128 * 132
    float* us = xsm + 128 * 132;        // 1024

    int o  = blockIdx.x;
    int ic = blockIdx.y;
    int bc = blockIdx.z;
    int t  = threadIdx.x;

    const float4* src = (const float4*)(cw + ((size_t)o * 1152 + ic * 128) * 128);
    for (int j = t; j < 4096; j += 256) {
        float4 v = src[j];
        int fo = j * 4;
        int il = fo >> 7, rem = fo & 127;
        *(float4*)(ws + il * 132 + rem) = v;
    }
    __syncthreads();

    int d = t & 15;
    int tr = t >> 4;

    for (int bl = 0; bl < 64; bl++) {
        int b = bc * 64 + bl;
        const float4* up = (const float4*)(g_u + ((size_t)b * 1152 + ic * 128) * 8);
        __syncthreads();
        *(float4*)(us + t * 4) = up[t];
        __syncthreads();

        __half* xout = g_xhat + (((size_t)(b * 10 + o) * 1152) + ic * 128) * 16;
#pragma unroll
        for (int isub = 0; isub < 8; isub++) {
            int il = isub * 16 + tr;
            const float* wr = ws + il * 132 + d * 8;
            const float* ur = us + il * 8;
            float acc = wr[0] * ur[0] + wr[1] * ur[1] + wr[2] * ur[2] + wr[3] * ur[3]
                      + wr[4] * ur[4] + wr[5] * ur[5] + wr[6] * ur[6] + wr[7] * ur[7];
            xout[il * 16 + d] = __float2half(acc);
        }
    }
}

// ---------------- softmax over output caps ----------------
__global__ __launch_bounds__(256) void softmax_c(const float* __restrict__ blog) {
    int idx = blockIdx.x * 256 + threadIdx.x;   // b*1152 + i
    if (idx >= 512 * 1152) return;
    int b = idx / 1152, i = idx - b * 1152;
    const float* blb = blog + (size_t)b * 10 * 1152 + i;
    float vals[10];
    float m = -1e30f;
#pragma unroll
    for (int o = 0; o < 10; o++) {
        vals[o] = blb[(size_t)o * 1152];
        m = fmaxf(m, vals[o]);
    }
    float sum = 0.f;
#pragma unroll
    for (int o = 0; o < 10; o++) { vals[o] = expf(vals[o] - m); sum += vals[o]; }
    float inv = 1.f / sum;
    float* cb = g_c + (size_t)b * 10 * 1152 + i;
#pragma unroll
    for (int o = 0; o < 10; o++) cb[(size_t)o * 1152] = vals[o] * inv;
}

// ---------------- fused routing A+B (fp16 x_hat) ----------------
template <int MODE>
__global__ __launch_bounds__(256) void routeAB_kernel(const float* __restrict__ blin_g,
                                                      float* __restrict__ blout_g) {
    extern __shared__ float sm[];
    float* xs = sm;                 // [1152][17]
    float* cs = sm + 1152 * 17;     // [1152]
    __shared__ float sred[256];
    __shared__ float sd[16];
    __shared__ float sscale;

    int bo = blockIdx.x;
    int t = threadIdx.x;

    const __half2* xg = (const __half2*)(g_xhat + (size_t)bo * 1152 * 16);
    for (int j = t; j < 1152 * 8; j += 256) {
        float2 f = __half22float2(xg[j]);
        int i = j >> 3, q = j & 7;
        float* dst = xs + i * 17 + q * 2;
        dst[0] = f.x; dst[1] = f.y;
    }

    if (MODE == 1) {
        const float* cg = g_c + (size_t)bo * 1152;
        for (int i = t; i < 1152; i += 256) cs[i] = cg[i];
    } else {
        for (int i = t; i < 1152; i += 256) cs[i] = 0.1f;
    }
    __syncthreads();

    int d = t & 15, g = t >> 4;
    float acc = 0.f;
    for (int i = g; i < 1152; i += 16)
        acc += cs[i] * xs[i * 17 + d];
    sred[t] = acc;
    __syncthreads();

    if (t < 16) {
        float s = 0.f;
#pragma unroll
        for (int gg = 0; gg < 16; gg++) s += sred[gg * 16 + t];
        sd[t] = s;
    }
    __syncthreads();

    if (t == 0) {
        float n2 = 0.f;
#pragma unroll
        for (int dd = 0; dd < 16; dd++) n2 += sd[dd] * sd[dd];
        float n = sqrtf(n2);
        sscale = n2 / (1.f + n2) / (n + 1e-8f);
    }
    __syncthreads();

    float scale = sscale;
    const float* blin = blin_g + (size_t)bo * 1152;
    float* blout = blout_g + (size_t)bo * 1152;
    for (int i = t; i < 1152; i += 256) {
        float dot = 0.f;
        const float* xr = xs + i * 17;
#pragma unroll
        for (int dd = 0; dd < 16; dd++) dot += sd[dd] * xr[dd];
        dot *= scale;
        blout[i] = (MODE == 1) ? (blin[i] + dot) : dot;
    }
}

// ---------------- final routing pass: c -> capsule lengths (fp16 x_hat) ----------------
__global__ __launch_bounds__(256) void routeFinal_kernel(float* __restrict__ out) {
    extern __shared__ float sm[];
    float* xs = sm;                 // [1152][17]
    float* cs = sm + 1152 * 17;     // [1152]
    __shared__ float sred[256];
    __shared__ float sd[16];

    int bo = blockIdx.x;
    int t = threadIdx.x;

    const __half2* xg = (const __half2*)(g_xhat + (size_t)bo * 1152 * 16);
    for (int j = t; j < 1152 * 8; j += 256) {
        float2 f = __half22float2(xg[j]);
        int i = j >> 3, q = j & 7;
        float* dst = xs + i * 17 + q * 2;
        dst[0] = f.x; dst[1] = f.y;
    }
    const float* cg = g_c + (size_t)bo * 1152;
    for (int i = t; i < 1152; i += 256) cs[i] = cg[i];
    __syncthreads();

    int d = t & 15, g = t >> 4;
    float acc = 0.f;
    for (int i = g; i < 1152; i += 16)
        acc += cs[i] * xs[i * 17 + d];
    sred[t] = acc;
    __syncthreads();

    if (t < 16) {
        float s = 0.f;
#pragma unroll
        for (int gg = 0; gg < 16; gg++) s += sred[gg * 16 + t];
        sd[t] = s;
    }
    __syncthreads();

    if (t == 0) {
        float n2 = 0.f;
#pragma unroll
        for (int dd = 0; dd < 16; dd++) n2 += sd[dd] * sd[dd];
        float n = sqrtf(n2);
        float scale = n2 / (1.f + n2) / (n + 1e-8f);
        out[bo] = scale * n;
    }
}

// ---------------- launch ----------------
extern "C" void kernel_launch(void* const* d_in, const int* in_sizes, int n_in,
                              void* d_out, int out_size) {
    const float* x   = (const float*)d_in[0];
    const float* w1  = (const float*)d_in[1];
    const float* b1  = (const float*)d_in[2];
    const float* w2  = (const float*)d_in[3];
    const float* b2  = (const float*)d_in[4];
    const float* cw  = (const float*)d_in[5];
    float* out = (float*)d_out;

    const int CONV2_SMEM = ASF0 + 2 * ASFSZ;             // 218112 B
    const int ROUTE_SMEM = (1152 * 17 + 1152) * 4;       // 82944 B
    const int W2_SMEM    = 256 * 81 * 4;                 // 82944 B
    const int XHAT_SMEM  = (128 * 132 + 1024) * 4;       // 71680 B
    cudaFuncSetAttribute(conv2_mma, cudaFuncAttributeMaxDynamicSharedMemorySize, CONV2_SMEM);
    cudaFuncSetAttribute(convert_w2, cudaFuncAttributeMaxDynamicSharedMemorySize, W2_SMEM);
    cudaFuncSetAttribute(xhat_kernel, cudaFuncAttributeMaxDynamicSharedMemorySize, XHAT_SMEM);
    cudaFuncSetAttribute(routeAB_kernel<0>, cudaFuncAttributeMaxDynamicSharedMemorySize, ROUTE_SMEM);
    cudaFuncSetAttribute(routeAB_kernel<1>, cudaFuncAttributeMaxDynamicSharedMemorySize, ROUTE_SMEM);
    cudaFuncSetAttribute(routeFinal_kernel, cudaFuncAttributeMaxDynamicSharedMemorySize, ROUTE_SMEM);

    float *blog0, *blog1;
    cudaGetSymbolAddress((void**)&blog0, g_blog0);
    cudaGetSymbolAddress((void**)&blog1, g_blog1);

    conv1_kernel<<<dim3(512, 2), 256>>>(x, w1, b1);
    convert_w2<<<256, 256, W2_SMEM>>>(w2);
    conv2_mma<<<dim3(2, 72), 384, CONV2_SMEM>>>(b2);
    squash_kernel<<<(512 * 1152 + 255) / 256, 256>>>();
    xhat_kernel<<<dim3(10, 9, 8), 256, XHAT_SMEM>>>(cw);

    routeAB_kernel<0><<<5120, 256, ROUTE_SMEM>>>(blog0, blog0);   // iter 0: uniform c
    softmax_c<<<(512 * 1152 + 255) / 256, 256>>>(blog0);
    routeAB_kernel<1><<<5120, 256, ROUTE_SMEM>>>(blog0, blog1);   // iter 1
    softmax_c<<<(512 * 1152 + 255) / 256, 256>>>(blog1);
    routeFinal_kernel<<<5120, 256, ROUTE_SMEM>>>(out);            // iter 2: lengths
}

// round 12
// speedup vs baseline: 3.0877x; 3.0877x over previous
#include <cuda_runtime.h>
#include <cuda_bf16.h>
#include <cuda_fp16.h>
#include <math.h>
#include <stdint.h>

// ---------------- scratch (static device globals; no runtime alloc) ----------------
__device__ __nv_bfloat16 g_h1_hi[(size_t)512 * 400 * 256];   // conv1 out hi, [b][pos][ci]
__device__ __nv_bfloat16 g_h1_lo[(size_t)512 * 400 * 256];   // conv1 out lo
__device__ __nv_bfloat16 g_w2_hi[81 * 256 * 256];            // pc_w hi, [kk][co][ci]
__device__ __nv_bfloat16 g_w2_lo[81 * 256 * 256];            // pc_w lo
__device__ float g_h2[512 * 9216];                           // conv2 out [b][i*8+k] (== [b][co*36+s])
__device__ __half g_xhat[(size_t)512 * 10 * 1152 * 16];      // votes [b][o][i][d] (fp16)
__device__ float g_blog0[512 * 10 * 1152];                   // routing logits ping
__device__ float g_blog1[512 * 10 * 1152];                   // routing logits pong
__device__ float g_c[512 * 10 * 1152];                       // softmax coefficients

// ---------------- PTX helpers (sm_80-era; compile on plain sm_103 target) ----------------
__device__ __forceinline__ uint32_t smem_u32(const void* p) {
    uint32_t a;
    asm("{ .reg .u64 t; cvta.to.shared.u64 t, %1; cvt.u32.u64 %0, t; }" : "=r"(a) : "l"(p));
    return a;
}
__device__ __forceinline__ void ldm_x4(uint32_t* r, uint32_t addr) {
    asm volatile("ldmatrix.sync.aligned.m8n8.x4.shared.b16 {%0,%1,%2,%3}, [%4];"
                 : "=r"(r[0]), "=r"(r[1]), "=r"(r[2]), "=r"(r[3]) : "r"(addr));
}
__device__ __forceinline__ void mma_bf16(float* c, const uint32_t* a, const uint32_t* b) {
    asm volatile("mma.sync.aligned.m16n8k16.row.col.f32.bf16.bf16.f32 "
                 "{%0,%1,%2,%3}, {%4,%5,%6,%7}, {%8,%9}, {%0,%1,%2,%3};"
                 : "+f"(c[0]), "+f"(c[1]), "+f"(c[2]), "+f"(c[3])
                 : "r"(a[0]), "r"(a[1]), "r"(a[2]), "r"(a[3]), "r"(b[0]), "r"(b[1]));
}
__device__ __forceinline__ void cp16(uint32_t dst, const void* src) {
    asm volatile("cp.async.cg.shared.global [%0], [%1], 16;" :: "r"(dst), "l"(src));
}
__device__ __forceinline__ void cp_commit() { asm volatile("cp.async.commit_group;" ::: "memory"); }
__device__ __forceinline__ void cp_wait0()  { asm volatile("cp.async.wait_group 0;" ::: "memory"); }

// ---------------- conv1: [512,1,28,28] -> channel-last bf16 hi/lo, ReLU ----------------
// grid (512 b, 4): each block computes 5 oh rows.
__global__ __launch_bounds__(256) void conv1_kernel(const float* __restrict__ x,
                                                    const float* __restrict__ w1,
                                                    const float* __restrict__ b1) {
    __shared__ float xs[784];
    int b  = blockIdx.x;
    int oh0 = blockIdx.y * 5;
    int co = threadIdx.x;
    const float* xb = x + (size_t)b * 784;
    for (int idx = co; idx < 784; idx += 256) xs[idx] = xb[idx];
    __syncthreads();

    float bias = b1[co];
    const float* wco = w1 + co * 81;

    for (int oh = oh0; oh < oh0 + 5; oh++) {
        float acc[20];
#pragma unroll
        for (int ow = 0; ow < 20; ow++) acc[ow] = 0.f;

        for (int kh = 0; kh < 9; kh++) {
            float xr[28];
#pragma unroll
            for (int c = 0; c < 28; c++) xr[c] = xs[(oh + kh) * 28 + c];
#pragma unroll
            for (int kw = 0; kw < 9; kw++) {
                float w = __ldg(&wco[kh * 9 + kw]);
#pragma unroll
                for (int ow = 0; ow < 20; ow++) acc[ow] += w * xr[ow + kw];
            }
        }
        size_t base = (((size_t)b * 400) + oh * 20) * 256 + co;
#pragma unroll
        for (int ow = 0; ow < 20; ow++) {
            float v = acc[ow] + bias;
            v = v > 0.f ? v : 0.f;
            __nv_bfloat16 h = __float2bfloat16(v);
            __nv_bfloat16 l = __float2bfloat16(v - __bfloat162float(h));
            g_h1_hi[base + (size_t)ow * 256] = h;
            g_h1_lo[base + (size_t)ow * 256] = l;
        }
    }
}

// ---------------- pc_w convert (coalesced): [co][ci][k] fp32 -> [kk][co][ci] bf16 hi/lo ----------------
__global__ __launch_bounds__(256) void convert_w2(const float* __restrict__ pcw) {
    extern __shared__ float ws[];    // [ci][81]
    int co = blockIdx.x;
    int t = threadIdx.x;
    const float* src = pcw + (size_t)co * 256 * 81;
    for (int idx = t; idx < 256 * 81; idx += 256) ws[idx] = src[idx];
    __syncthreads();
    int ci = t;
    for (int k = 0; k < 81; k++) {
        float v = ws[ci * 81 + k];
        __nv_bfloat16 h = __float2bfloat16(v);
        __nv_bfloat16 l = __float2bfloat16(v - __bfloat162float(h));
        size_t o = ((size_t)k * 256 + co) * 256 + ci;
        g_w2_hi[o] = h;
        g_w2_lo[o] = l;
    }
}

// ---------------- conv2 via HMMA implicit GEMM, cp.async double-buffered (R10 proven) ----------------
#define LDK 72
#define BUFSZ 110592
#define AHI 0
#define ALO 18432
#define BHI 36864
#define BLO 73728
#define NITER 324
__global__ __launch_bounds__(256, 1) void conv2_mma(const float* __restrict__ pcb) {
    extern __shared__ char smem[];
    uint32_t sb = smem_u32(smem);
    int tid = threadIdx.x;
    int wid = tid >> 5;
    int lane = tid & 31;
    int mtile = blockIdx.x;      // 0..1   (co block of 128)
    int ntile = blockIdx.y;      // 0..71  (pos block of 256)

    int wm = wid & 3;
    int wn = wid >> 2;

    int seg = tid & 7;
    int rbase = tid >> 3;
    uint32_t adst[4];
    uint32_t aoff[4];
#pragma unroll
    for (int j = 0; j < 4; j++) {
        int row = rbase + j * 32;
        adst[j] = (uint32_t)(row * LDK + seg * 8) * 2;
        aoff[j] = (uint32_t)((mtile * 128 + row) * 256 + seg * 8);
    }
    uint32_t bdst[8];
    size_t gb[8];
#pragma unroll
    for (int j = 0; j < 8; j++) {
        int row = rbase + j * 32;
        bdst[j] = (uint32_t)(row * LDK + seg * 8) * 2;
        int p = ntile * 256 + row;
        int b = p / 36;
        int s = p - b * 36;
        int oh = s / 6, ow = s - oh * 6;
        gb[j] = ((size_t)b * 400 + oh * 40 + ow * 2) * 256 + seg * 8;
    }

    float acc[2][16][4];
#pragma unroll
    for (int mt = 0; mt < 2; mt++)
#pragma unroll
        for (int nt = 0; nt < 16; nt++)
#pragma unroll
            for (int j = 0; j < 4; j++) acc[mt][nt][j] = 0.f;

    int rowA = lane & 15;
    int kgA  = (lane >> 4) << 3;
    int rowB = ((lane >> 4) << 3) + (lane & 7);
    int kgB  = ((lane >> 3) & 1) << 3;

#define STAGE(IT, BSEL) do {                                                        \
        int _it = (IT);                                                             \
        int _cb = (_it / 81) << 6;                                                  \
        int _kk = _it - (_it / 81) * 81;                                            \
        int _kh = _kk / 9, _kw = _kk - _kh * 9;                                     \
        uint32_t _bu = sb + (BSEL) * BUFSZ;                                         \
        size_t _abase = ((size_t)_kk * 256) * 256 + _cb;                            \
        size_t _boff = (size_t)(_kh * 20 + _kw) * 256 + _cb;                        \
        _Pragma("unroll")                                                           \
        for (int j = 0; j < 4; j++) {                                               \
            size_t _s = _abase + aoff[j];                                           \
            cp16(_bu + AHI + adst[j], (const char*)g_w2_hi + _s * 2);               \
            cp16(_bu + ALO + adst[j], (const char*)g_w2_lo + _s * 2);               \
        }                                                                           \
        _Pragma("unroll")                                                           \
        for (int j = 0; j < 8; j++) {                                               \
            size_t _s = gb[j] + _boff;                                              \
            cp16(_bu + BHI + bdst[j], (const char*)g_h1_hi + _s * 2);               \
            cp16(_bu + BLO + bdst[j], (const char*)g_h1_lo + _s * 2);               \
        }                                                                           \
    } while (0)

    STAGE(0, 0);
    cp_commit();
    cp_wait0();
    __syncthreads();

    for (int it = 0; it < NITER; it++) {
        if (it + 1 < NITER) { STAGE(it + 1, (it + 1) & 1); cp_commit(); }

        uint32_t bu = sb + (it & 1) * BUFSZ;
#pragma unroll
        for (int ks = 0; ks < 4; ks++) {
            int k0 = ks * 16;
            uint32_t ahi[2][4], alo[2][4];
#pragma unroll
            for (int mt = 0; mt < 2; mt++) {
                uint32_t arow = (uint32_t)((wm * 32 + mt * 16 + rowA) * LDK + k0 + kgA) * 2;
                ldm_x4(ahi[mt], bu + AHI + arow);
                ldm_x4(alo[mt], bu + ALO + arow);
            }
#pragma unroll
            for (int nh = 0; nh < 4; nh++) {
                uint32_t bhi[4][2], blo[4][2];
#pragma unroll
                for (int nq = 0; nq < 2; nq++) {
                    uint32_t brow = (uint32_t)((wn * 128 + nh * 32 + nq * 16 + rowB) * LDK + k0 + kgB) * 2;
                    uint32_t t4[4];
                    ldm_x4(t4, bu + BHI + brow);
                    bhi[2 * nq][0] = t4[0]; bhi[2 * nq][1] = t4[1];
                    bhi[2 * nq + 1][0] = t4[2]; bhi[2 * nq + 1][1] = t4[3];
                    ldm_x4(t4, bu + BLO + brow);
                    blo[2 * nq][0] = t4[0]; blo[2 * nq][1] = t4[1];
                    blo[2 * nq + 1][0] = t4[2]; blo[2 * nq + 1][1] = t4[3];
                }
#pragma unroll
                for (int mt = 0; mt < 2; mt++)
#pragma unroll
                    for (int nq = 0; nq < 4; nq++) {
                        int nt = nh * 4 + nq;
                        mma_bf16(acc[mt][nt], ahi[mt], bhi[nq]);
                        mma_bf16(acc[mt][nt], ahi[mt], blo[nq]);
                        mma_bf16(acc[mt][nt], alo[mt], bhi[nq]);
                    }
            }
        }
        if (it + 1 < NITER) cp_wait0();
        __syncthreads();
    }

    int r0 = lane >> 2, cp = lane & 3;
#pragma unroll
    for (int mt = 0; mt < 2; mt++) {
#pragma unroll
        for (int half = 0; half < 2; half++) {
            int m = wm * 32 + mt * 16 + r0 + half * 8;
            int co = mtile * 128 + m;
            float bias = pcb[co];
#pragma unroll
            for (int nt = 0; nt < 16; nt++) {
#pragma unroll
                for (int e = 0; e < 2; e++) {
                    int p = ntile * 256 + wn * 128 + nt * 8 + 2 * cp + e;
                    int b = p / 36;
                    int s = p - b * 36;
                    g_h2[(size_t)b * 9216 + co * 36 + s] = acc[mt][nt][half * 2 + e] + bias;
                }
            }
        }
    }
}

// ---------------- votes with fused squash: h2 slab -> squash (shfl pair) -> x_hat fp16 ----------------
// grid (10 o, 9 ichunk, 8 bchunk); o fastest -> 10 consecutive blocks share each h2 slab in L2.
__global__ __launch_bounds__(256) void xhat_kernel(const float* __restrict__ cw) {
    extern __shared__ float xsm[];
    float* ws = xsm;                    // 128 * 132  (caps_w tile, padded)
    float* us = xsm + 128 * 132;        // 1024       (squashed u slab)

    int o  = blockIdx.x;
    int ic = blockIdx.y;
    int bc = blockIdx.z;
    int t  = threadIdx.x;

    const float4* src = (const float4*)(cw + ((size_t)o * 1152 + ic * 128) * 128);
    for (int j = t; j < 4096; j += 256) {
        float4 v = src[j];
        int fo = j * 4;
        int il = fo >> 7, rem = fo & 127;
        *(float4*)(ws + il * 132 + rem) = v;
    }
    __syncthreads();

    int d = t & 15;
    int tr = t >> 4;

    for (int bl = 0; bl < 64; bl++) {
        int b = bc * 64 + bl;
        // load h2 slab (same flat layout as u) and squash in-register:
        // capsule = 2 adjacent float4s; pair-reduce norm via shfl_xor(1).
        const float4* hp = (const float4*)(g_h2 + (size_t)b * 9216 + (size_t)ic * 1024);
        __syncthreads();
        {
            float4 v = hp[t];
            float dp = v.x * v.x + v.y * v.y + v.z * v.z + v.w * v.w;
            float n2 = dp + __shfl_xor_sync(0xffffffffu, dp, 1);
            float n = sqrtf(n2);
            float scale = n2 / (1.f + n2) / (n + 1e-8f);
            v.x *= scale; v.y *= scale; v.z *= scale; v.w *= scale;
            *(float4*)(us + t * 4) = v;
        }
        __syncthreads();

        __half* xout = g_xhat + (((size_t)(b * 10 + o) * 1152) + ic * 128) * 16;
#pragma unroll
        for (int isub = 0; isub < 8; isub++) {
            int il = isub * 16 + tr;
            const float* wr = ws + il * 132 + d * 8;
            const float* ur = us + il * 8;
            float acc = wr[0] * ur[0] + wr[1] * ur[1] + wr[2] * ur[2] + wr[3] * ur[3]
                      + wr[4] * ur[4] + wr[5] * ur[5] + wr[6] * ur[6] + wr[7] * ur[7];
            xout[il * 16 + d] = __float2half(acc);
        }
    }
}

// ---------------- softmax over output caps ----------------
__global__ __launch_bounds__(256) void softmax_c(const float* __restrict__ blog) {
    int idx = blockIdx.x * 256 + threadIdx.x;   // b*1152 + i
    if (idx >= 512 * 1152) return;
    int b = idx / 1152, i = idx - b * 1152;
    const float* blb = blog + (size_t)b * 10 * 1152 + i;
    float vals[10];
    float m = -1e30f;
#pragma unroll
    for (int o = 0; o < 10; o++) {
        vals[o] = blb[(size_t)o * 1152];
        m = fmaxf(m, vals[o]);
    }
    float sum = 0.f;
#pragma unroll
    for (int o = 0; o < 10; o++) { vals[o] = expf(vals[o] - m); sum += vals[o]; }
    float inv = 1.f / sum;
    float* cb = g_c + (size_t)b * 10 * 1152 + i;
#pragma unroll
    for (int o = 0; o < 10; o++) cb[(size_t)o * 1152] = vals[o] * inv;
}

// ---------------- fused routing A+B (fp16 x_hat) ----------------
template <int MODE>
__global__ __launch_bounds__(256) void routeAB_kernel(const float* __restrict__ blin_g,
                                                      float* __restrict__ blout_g) {
    extern __shared__ float sm[];
    float* xs = sm;                 // [1152][17]
    float* cs = sm + 1152 * 17;     // [1152]
    __shared__ float sred[256];
    __shared__ float sd[16];
    __shared__ float sscale;

    int bo = blockIdx.x;
    int t = threadIdx.x;

    const __half2* xg = (const __half2*)(g_xhat + (size_t)bo * 1152 * 16);
    for (int j = t; j < 1152 * 8; j += 256) {
        float2 f = __half22float2(xg[j]);
        int i = j >> 3, q = j & 7;
        float* dst = xs + i * 17 + q * 2;
        dst[0] = f.x; dst[1] = f.y;
    }

    if (MODE == 1) {
        const float* cg = g_c + (size_t)bo * 1152;
        for (int i = t; i < 1152; i += 256) cs[i] = cg[i];
    } else {
        for (int i = t; i < 1152; i += 256) cs[i] = 0.1f;
    }
    __syncthreads();

    int d = t & 15, g = t >> 4;
    float acc = 0.f;
    for (int i = g; i < 1152; i += 16)
        acc += cs[i] * xs[i * 17 + d];
    sred[t] = acc;
    __syncthreads();

    if (t < 16) {
        float s = 0.f;
#pragma unroll
        for (int gg = 0; gg < 16; gg++) s += sred[gg * 16 + t];
        sd[t] = s;
    }
    __syncthreads();

    if (t == 0) {
        float n2 = 0.f;
#pragma unroll
        for (int dd = 0; dd < 16; dd++) n2 += sd[dd] * sd[dd];
        float n = sqrtf(n2);
        sscale = n2 / (1.f + n2) / (n + 1e-8f);
    }
    __syncthreads();

    float scale = sscale;
    const float* blin = blin_g + (size_t)bo * 1152;
    float* blout = blout_g + (size_t)bo * 1152;
    for (int i = t; i < 1152; i += 256) {
        float dot = 0.f;
        const float* xr = xs + i * 17;
#pragma unroll
        for (int dd = 0; dd < 16; dd++) dot += sd[dd] * xr[dd];
        dot *= scale;
        blout[i] = (MODE == 1) ? (blin[i] + dot) : dot;
    }
}

// ---------------- final routing pass: c -> capsule lengths (fp16 x_hat) ----------------
__global__ __launch_bounds__(256) void routeFinal_kernel(float* __restrict__ out) {
    extern __shared__ float sm[];
    float* xs = sm;                 // [1152][17]
    float* cs = sm + 1152 * 17;     // [1152]
    __shared__ float sred[256];
    __shared__ float sd[16];

    int bo = blockIdx.x;
    int t = threadIdx.x;

    const __half2* xg = (const __half2*)(g_xhat + (size_t)bo * 1152 * 16);
    for (int j = t; j < 1152 * 8; j += 256) {
        float2 f = __half22float2(xg[j]);
        int i = j >> 3, q = j & 7;
        float* dst = xs + i * 17 + q * 2;
        dst[0] = f.x; dst[1] = f.y;
    }
    const float* cg = g_c + (size_t)bo * 1152;
    for (int i = t; i < 1152; i += 256) cs[i] = cg[i];
    __syncthreads();

    int d = t & 15, g = t >> 4;
    float acc = 0.f;
    for (int i = g; i < 1152; i += 16)
        acc += cs[i] * xs[i * 17 + d];
    sred[t] = acc;
    __syncthreads();

    if (t < 16) {
        float s = 0.f;
#pragma unroll
        for (int gg = 0; gg < 16; gg++) s += sred[gg * 16 + t];
        sd[t] = s;
    }
    __syncthreads();

    if (t == 0) {
        float n2 = 0.f;
#pragma unroll
        for (int dd = 0; dd < 16; dd++) n2 += sd[dd] * sd[dd];
        float n = sqrtf(n2);
        float scale = n2 / (1.f + n2) / (n + 1e-8f);
        out[bo] = scale * n;
    }
}

// ---------------- launch ----------------
extern "C" void kernel_launch(void* const* d_in, const int* in_sizes, int n_in,
                              void* d_out, int out_size) {
    const float* x   = (const float*)d_in[0];
    const float* w1  = (const float*)d_in[1];
    const float* b1  = (const float*)d_in[2];
    const float* w2  = (const float*)d_in[3];
    const float* b2  = (const float*)d_in[4];
    const float* cw  = (const float*)d_in[5];
    float* out = (float*)d_out;

    const int CONV2_SMEM = 2 * BUFSZ;                    // 221184 B
    const int ROUTE_SMEM = (1152 * 17 + 1152) * 4;       // 82944 B
    const int W2_SMEM    = 256 * 81 * 4;                 // 82944 B
    const int XHAT_SMEM  = (128 * 132 + 1024) * 4;       // 71680 B
    cudaFuncSetAttribute(conv2_mma, cudaFuncAttributeMaxDynamicSharedMemorySize, CONV2_SMEM);
    cudaFuncSetAttribute(convert_w2, cudaFuncAttributeMaxDynamicSharedMemorySize, W2_SMEM);
    cudaFuncSetAttribute(xhat_kernel, cudaFuncAttributeMaxDynamicSharedMemorySize, XHAT_SMEM);
    cudaFuncSetAttribute(routeAB_kernel<0>, cudaFuncAttributeMaxDynamicSharedMemorySize, ROUTE_SMEM);
    cudaFuncSetAttribute(routeAB_kernel<1>, cudaFuncAttributeMaxDynamicSharedMemorySize, ROUTE_SMEM);
    cudaFuncSetAttribute(routeFinal_kernel, cudaFuncAttributeMaxDynamicSharedMemorySize, ROUTE_SMEM);

    float *blog0, *blog1;
    cudaGetSymbolAddress((void**)&blog0, g_blog0);
    cudaGetSymbolAddress((void**)&blog1, g_blog1);

    conv1_kernel<<<dim3(512, 4), 256>>>(x, w1, b1);
    convert_w2<<<256, 256, W2_SMEM>>>(w2);
    conv2_mma<<<dim3(2, 72), 256, CONV2_SMEM>>>(b2);
    xhat_kernel<<<dim3(10, 9, 8), 256, XHAT_SMEM>>>(cw);

    routeAB_kernel<0><<<5120, 256, ROUTE_SMEM>>>(blog0, blog0);   // iter 0: uniform c
    softmax_c<<<(512 * 1152 + 255) / 256, 256>>>(blog0);
    routeAB_kernel<1><<<5120, 256, ROUTE_SMEM>>>(blog0, blog1);   // iter 1
    softmax_c<<<(512 * 1152 + 255) / 256, 256>>>(blog1);
    routeFinal_kernel<<<5120, 256, ROUTE_SMEM>>>(out);            // iter 2: lengths
}

// round 13
// speedup vs baseline: 3.1693x; 1.0264x over previous
#include <cuda_runtime.h>
#include <cuda_bf16.h>
#include <cuda_fp16.h>
#include <math.h>
#include <stdint.h>

// ---------------- scratch (static device globals; no runtime alloc) ----------------
__device__ __nv_bfloat16 g_h1_hi[(size_t)512 * 400 * 256];   // conv1 out hi, [b][pos][ci]
__device__ __nv_bfloat16 g_h1_lo[(size_t)512 * 400 * 256];   // conv1 out lo
__device__ __nv_bfloat16 g_w2_hi[81 * 256 * 256];            // pc_w hi, [kk][co][ci]
__device__ __nv_bfloat16 g_w2_lo[81 * 256 * 256];            // pc_w lo
__device__ float g_h2[512 * 9216];                           // conv2 out [b][i*8+k]
__device__ __half g_xhat[(size_t)512 * 10 * 1152 * 16];      // votes [b][o][i][d] (fp16)
__device__ float g_blog0[512 * 10 * 1152];                   // routing logits ping
__device__ float g_blog1[512 * 10 * 1152];                   // routing logits pong
__device__ float g_c[512 * 10 * 1152];                       // softmax coefficients

// ---------------- PTX helpers (sm_80-era; compile on plain sm_103 target) ----------------
__device__ __forceinline__ uint32_t smem_u32(const void* p) {
    uint32_t a;
    asm("{ .reg .u64 t; cvta.to.shared.u64 t, %1; cvt.u32.u64 %0, t; }" : "=r"(a) : "l"(p));
    return a;
}
__device__ __forceinline__ void ldm_x4(uint32_t* r, uint32_t addr) {
    asm volatile("ldmatrix.sync.aligned.m8n8.x4.shared.b16 {%0,%1,%2,%3}, [%4];"
                 : "=r"(r[0]), "=r"(r[1]), "=r"(r[2]), "=r"(r[3]) : "r"(addr));
}
__device__ __forceinline__ void mma_bf16(float* c, const uint32_t* a, const uint32_t* b) {
    asm volatile("mma.sync.aligned.m16n8k16.row.col.f32.bf16.bf16.f32 "
                 "{%0,%1,%2,%3}, {%4,%5,%6,%7}, {%8,%9}, {%0,%1,%2,%3};"
                 : "+f"(c[0]), "+f"(c[1]), "+f"(c[2]), "+f"(c[3])
                 : "r"(a[0]), "r"(a[1]), "r"(a[2]), "r"(a[3]), "r"(b[0]), "r"(b[1]));
}
__device__ __forceinline__ void cp16(uint32_t dst, const void* src) {
    asm volatile("cp.async.cg.shared.global [%0], [%1], 16;" :: "r"(dst), "l"(src));
}
__device__ __forceinline__ void cp_commit() { asm volatile("cp.async.commit_group;" ::: "memory"); }
__device__ __forceinline__ void cp_wait0()  { asm volatile("cp.async.wait_group 0;" ::: "memory"); }

// ---------------- conv1: [512,1,28,28] -> channel-last bf16 hi/lo, ReLU ----------------
__global__ __launch_bounds__(256) void conv1_kernel(const float* __restrict__ x,
                                                    const float* __restrict__ w1,
                                                    const float* __restrict__ b1) {
    __shared__ float xs[784];
    int b  = blockIdx.x;
    int oh0 = blockIdx.y * 5;
    int co = threadIdx.x;
    const float* xb = x + (size_t)b * 784;
    for (int idx = co; idx < 784; idx += 256) xs[idx] = xb[idx];
    __syncthreads();

    float bias = b1[co];
    const float* wco = w1 + co * 81;

    for (int oh = oh0; oh < oh0 + 5; oh++) {
        float acc[20];
#pragma unroll
        for (int ow = 0; ow < 20; ow++) acc[ow] = 0.f;

        for (int kh = 0; kh < 9; kh++) {
            float xr[28];
#pragma unroll
            for (int c = 0; c < 28; c++) xr[c] = xs[(oh + kh) * 28 + c];
#pragma unroll
            for (int kw = 0; kw < 9; kw++) {
                float w = __ldg(&wco[kh * 9 + kw]);
#pragma unroll
                for (int ow = 0; ow < 20; ow++) acc[ow] += w * xr[ow + kw];
            }
        }
        size_t base = (((size_t)b * 400) + oh * 20) * 256 + co;
#pragma unroll
        for (int ow = 0; ow < 20; ow++) {
            float v = acc[ow] + bias;
            v = v > 0.f ? v : 0.f;
            __nv_bfloat16 h = __float2bfloat16(v);
            __nv_bfloat16 l = __float2bfloat16(v - __bfloat162float(h));
            g_h1_hi[base + (size_t)ow * 256] = h;
            g_h1_lo[base + (size_t)ow * 256] = l;
        }
    }
}

// ---------------- pc_w convert (coalesced): [co][ci][k] fp32 -> [kk][co][ci] bf16 hi/lo ----------------
__global__ __launch_bounds__(256) void convert_w2(const float* __restrict__ pcw) {
    extern __shared__ float ws[];    // [ci][81]
    int co = blockIdx.x;
    int t = threadIdx.x;
    const float* src = pcw + (size_t)co * 256 * 81;
    for (int idx = t; idx < 256 * 81; idx += 256) ws[idx] = src[idx];
    __syncthreads();
    int ci = t;
    for (int k = 0; k < 81; k++) {
        float v = ws[ci * 81 + k];
        __nv_bfloat16 h = __float2bfloat16(v);
        __nv_bfloat16 l = __float2bfloat16(v - __bfloat162float(h));
        size_t o = ((size_t)k * 256 + co) * 256 + ci;
        g_w2_hi[o] = h;
        g_w2_lo[o] = l;
    }
}

// ---------------- conv2 via HMMA implicit GEMM, cp.async double-buffered ----------------
#define LDK 72
#define BUFSZ 110592
#define AHI 0
#define ALO 18432
#define BHI 36864
#define BLO 73728
#define NITER 324
__global__ __launch_bounds__(256, 1) void conv2_mma(const float* __restrict__ pcb) {
    extern __shared__ char smem[];
    uint32_t sb = smem_u32(smem);
    int tid = threadIdx.x;
    int wid = tid >> 5;
    int lane = tid & 31;
    int mtile = blockIdx.x;
    int ntile = blockIdx.y;

    int wm = wid & 3;
    int wn = wid >> 2;

    int seg = tid & 7;
    int rbase = tid >> 3;
    uint32_t adst[4];
    uint32_t aoff[4];
#pragma unroll
    for (int j = 0; j < 4; j++) {
        int row = rbase + j * 32;
        adst[j] = (uint32_t)(row * LDK + seg * 8) * 2;
        aoff[j] = (uint32_t)((mtile * 128 + row) * 256 + seg * 8);
    }
    uint32_t bdst[8];
    size_t gb[8];
#pragma unroll
    for (int j = 0; j < 8; j++) {
        int row = rbase + j * 32;
        bdst[j] = (uint32_t)(row * LDK + seg * 8) * 2;
        int p = ntile * 256 + row;
        int b = p / 36;
        int s = p - b * 36;
        int oh = s / 6, ow = s - oh * 6;
        gb[j] = ((size_t)b * 400 + oh * 40 + ow * 2) * 256 + seg * 8;
    }

    float acc[2][16][4];
#pragma unroll
    for (int mt = 0; mt < 2; mt++)
#pragma unroll
        for (int nt = 0; nt < 16; nt++)
#pragma unroll
            for (int j = 0; j < 4; j++) acc[mt][nt][j] = 0.f;

    int rowA = lane & 15;
    int kgA  = (lane >> 4) << 3;
    int rowB = ((lane >> 4) << 3) + (lane & 7);
    int kgB  = ((lane >> 3) & 1) << 3;

#define STAGE(IT, BSEL) do {                                                        \
        int _it = (IT);                                                             \
        int _cb = (_it / 81) << 6;                                                  \
        int _kk = _it - (_it / 81) * 81;                                            \
        int _kh = _kk / 9, _kw = _kk - _kh * 9;                                     \
        uint32_t _bu = sb + (BSEL) * BUFSZ;                                         \
        size_t _abase = ((size_t)_kk * 256) * 256 + _cb;                            \
        size_t _boff = (size_t)(_kh * 20 + _kw) * 256 + _cb;                        \
        _Pragma("unroll")                                                           \
        for (int j = 0; j < 4; j++) {                                               \
            size_t _s = _abase + aoff[j];                                           \
            cp16(_bu + AHI + adst[j], (const char*)g_w2_hi + _s * 2);               \
            cp16(_bu + ALO + adst[j], (const char*)g_w2_lo + _s * 2);               \
        }                                                                           \
        _Pragma("unroll")                                                           \
        for (int j = 0; j < 8; j++) {                                               \
            size_t _s = gb[j] + _boff;                                              \
            cp16(_bu + BHI + bdst[j], (const char*)g_h1_hi + _s * 2);               \
            cp16(_bu + BLO + bdst[j], (const char*)g_h1_lo + _s * 2);               \
        }                                                                           \
    } while (0)

    STAGE(0, 0);
    cp_commit();
    cp_wait0();
    __syncthreads();

    for (int it = 0; it < NITER; it++) {
        if (it + 1 < NITER) { STAGE(it + 1, (it + 1) & 1); cp_commit(); }

        uint32_t bu = sb + (it & 1) * BUFSZ;
#pragma unroll
        for (int ks = 0; ks < 4; ks++) {
            int k0 = ks * 16;
            uint32_t ahi[2][4], alo[2][4];
#pragma unroll
            for (int mt = 0; mt < 2; mt++) {
                uint32_t arow = (uint32_t)((wm * 32 + mt * 16 + rowA) * LDK + k0 + kgA) * 2;
                ldm_x4(ahi[mt], bu + AHI + arow);
                ldm_x4(alo[mt], bu + ALO + arow);
            }
#pragma unroll
            for (int nh = 0; nh < 4; nh++) {
                uint32_t bhi[4][2], blo[4][2];
#pragma unroll
                for (int nq = 0; nq < 2; nq++) {
                    uint32_t brow = (uint32_t)((wn * 128 + nh * 32 + nq * 16 + rowB) * LDK + k0 + kgB) * 2;
                    uint32_t t4[4];
                    ldm_x4(t4, bu + BHI + brow);
                    bhi[2 * nq][0] = t4[0]; bhi[2 * nq][1] = t4[1];
                    bhi[2 * nq + 1][0] = t4[2]; bhi[2 * nq + 1][1] = t4[3];
                    ldm_x4(t4, bu + BLO + brow);
                    blo[2 * nq][0] = t4[0]; blo[2 * nq][1] = t4[1];
                    blo[2 * nq + 1][0] = t4[2]; blo[2 * nq + 1][1] = t4[3];
                }
#pragma unroll
                for (int mt = 0; mt < 2; mt++)
#pragma unroll
                    for (int nq = 0; nq < 4; nq++) {
                        int nt = nh * 4 + nq;
                        mma_bf16(acc[mt][nt], ahi[mt], bhi[nq]);
                        mma_bf16(acc[mt][nt], ahi[mt], blo[nq]);
                        mma_bf16(acc[mt][nt], alo[mt], bhi[nq]);
                    }
            }
        }
        if (it + 1 < NITER) cp_wait0();
        __syncthreads();
    }

    int r0 = lane >> 2, cp = lane & 3;
#pragma unroll
    for (int mt = 0; mt < 2; mt++) {
#pragma unroll
        for (int half = 0; half < 2; half++) {
            int m = wm * 32 + mt * 16 + r0 + half * 8;
            int co = mtile * 128 + m;
            float bias = pcb[co];
#pragma unroll
            for (int nt = 0; nt < 16; nt++) {
#pragma unroll
                for (int e = 0; e < 2; e++) {
                    int p = ntile * 256 + wn * 128 + nt * 8 + 2 * cp + e;
                    int b = p / 36;
                    int s = p - b * 36;
                    g_h2[(size_t)b * 9216 + co * 36 + s] = acc[mt][nt][half * 2 + e] + bias;
                }
            }
        }
    }
}

// ---------------- votes + fused squash, conflict-free smem layout ----------------
// caps_w restaged as [k2][il][d] float2 (k-pair-major): compute reads are bank-conflict-free.
// grid (10 o, 9 ichunk, 8 bchunk); o fastest -> h2 slab L2 reuse.
__global__ __launch_bounds__(256) void xhat_kernel(const float* __restrict__ cw) {
    extern __shared__ float xsm[];
    float* wt = xsm;                    // 4 k2-planes * 2048 (il*16+d) * 2 = 16384 floats
    float* us = xsm + 16384;            // 1024 floats (squashed u slab)

    int o  = blockIdx.x;
    int ic = blockIdx.y;
    int bc = blockIdx.z;
    int t  = threadIdx.x;

    // stage caps_w tile transposed: cw float4 j covers (il, d, k0..k0+3), k0 in {0,4}
    const float4* src = (const float4*)(cw + ((size_t)o * 1152 + ic * 128) * 128);
    for (int j = t; j < 4096; j += 256) {
        float4 v = src[j];
        int fo = j * 4;
        int il = fo >> 7, rem = fo & 127;
        int d = rem >> 3, k0 = rem & 7;              // k0 = 0 or 4
        int base = ((k0 >> 1) * 2048 + il * 16 + d) * 2;
        *(float2*)(wt + base)        = make_float2(v.x, v.y);   // k0, k0+1
        *(float2*)(wt + base + 4096) = make_float2(v.z, v.w);   // k0+2, k0+3
    }
    __syncthreads();

    int d = t & 15;
    int tr = t >> 4;

    for (int bl = 0; bl < 64; bl++) {
        int b = bc * 64 + bl;
        // load h2 slab and squash in-register (capsule = 2 adjacent float4, shfl pair)
        const float4* hp = (const float4*)(g_h2 + (size_t)b * 9216 + (size_t)ic * 1024);
        __syncthreads();
        {
            float4 v = hp[t];
            float dp = v.x * v.x + v.y * v.y + v.z * v.z + v.w * v.w;
            float n2 = dp + __shfl_xor_sync(0xffffffffu, dp, 1);
            float n = sqrtf(n2);
            float scale = n2 / (1.f + n2) / (n + 1e-8f);
            v.x *= scale; v.y *= scale; v.z *= scale; v.w *= scale;
            *(float4*)(us + t * 4) = v;
        }
        __syncthreads();

        __half* xout = g_xhat + (((size_t)(b * 10 + o) * 1152) + ic * 128) * 16;
#pragma unroll
        for (int isub = 0; isub < 8; isub++) {
            int il = isub * 16 + tr;
            int wi = (il * 16 + d) * 2;
            float2 w01 = *(const float2*)(wt + wi);
            float2 w23 = *(const float2*)(wt + wi + 4096);
            float2 w45 = *(const float2*)(wt + wi + 8192);
            float2 w67 = *(const float2*)(wt + wi + 12288);
            float4 u0 = *(const float4*)(us + il * 8);
            float4 u1 = *(const float4*)(us + il * 8 + 4);
            float acc = w01.x * u0.x + w01.y * u0.y + w23.x * u0.z + w23.y * u0.w
                      + w45.x * u1.x + w45.y * u1.y + w67.x * u1.z + w67.y * u1.w;
            xout[il * 16 + d] = __float2half(acc);
        }
    }
}

// ---------------- softmax over output caps ----------------
__global__ __launch_bounds__(256) void softmax_c(const float* __restrict__ blog) {
    int idx = blockIdx.x * 256 + threadIdx.x;
    if (idx >= 512 * 1152) return;
    int b = idx / 1152, i = idx - b * 1152;
    const float* blb = blog + (size_t)b * 10 * 1152 + i;
    float vals[10];
    float m = -1e30f;
#pragma unroll
    for (int o = 0; o < 10; o++) {
        vals[o] = blb[(size_t)o * 1152];
        m = fmaxf(m, vals[o]);
    }
    float sum = 0.f;
#pragma unroll
    for (int o = 0; o < 10; o++) { vals[o] = expf(vals[o] - m); sum += vals[o]; }
    float inv = 1.f / sum;
    float* cb = g_c + (size_t)b * 10 * 1152 + i;
#pragma unroll
    for (int o = 0; o < 10; o++) cb[(size_t)o * 1152] = vals[o] * inv;
}

// ---------------- fused routing A+B (fp16 x_hat) ----------------
template <int MODE>
__global__ __launch_bounds__(256) void routeAB_kernel(const float* __restrict__ blin_g,
                                                      float* __restrict__ blout_g) {
    extern __shared__ float sm[];
    float* xs = sm;                 // [1152][17]
    float* cs = sm + 1152 * 17;     // [1152]
    __shared__ float sred[256];
    __shared__ float sd[16];
    __shared__ float sscale;

    int bo = blockIdx.x;
    int t = threadIdx.x;

    const __half2* xg = (const __half2*)(g_xhat + (size_t)bo * 1152 * 16);
    for (int j = t; j < 1152 * 8; j += 256) {
        float2 f = __half22float2(xg[j]);
        int i = j >> 3, q = j & 7;
        float* dst = xs + i * 17 + q * 2;
        dst[0] = f.x; dst[1] = f.y;
    }

    if (MODE == 1) {
        const float* cg = g_c + (size_t)bo * 1152;
        for (int i = t; i < 1152; i += 256) cs[i] = cg[i];
    } else {
        for (int i = t; i < 1152; i += 256) cs[i] = 0.1f;
    }
    __syncthreads();

    int d = t & 15, g = t >> 4;
    float acc = 0.f;
    for (int i = g; i < 1152; i += 16)
        acc += cs[i] * xs[i * 17 + d];
    sred[t] = acc;
    __syncthreads();

    if (t < 16) {
        float s = 0.f;
#pragma unroll
        for (int gg = 0; gg < 16; gg++) s += sred[gg * 16 + t];
        sd[t] = s;
    }
    __syncthreads();

    if (t == 0) {
        float n2 = 0.f;
#pragma unroll
        for (int dd = 0; dd < 16; dd++) n2 += sd[dd] * sd[dd];
        float n = sqrtf(n2);
        sscale = n2 / (1.f + n2) / (n + 1e-8f);
    }
    __syncthreads();

    float scale = sscale;
    const float* blin = blin_g + (size_t)bo * 1152;
    float* blout = blout_g + (size_t)bo * 1152;
    for (int i = t; i < 1152; i += 256) {
        float dot = 0.f;
        const float* xr = xs + i * 17;
#pragma unroll
        for (int dd = 0; dd < 16; dd++) dot += sd[dd] * xr[dd];
        dot *= scale;
        blout[i] = (MODE == 1) ? (blin[i] + dot) : dot;
    }
}

// ---------------- final routing pass: c -> capsule lengths (fp16 x_hat) ----------------
__global__ __launch_bounds__(256) void routeFinal_kernel(float* __restrict__ out) {
    extern __shared__ float sm[];
    float* xs = sm;                 // [1152][17]
    float* cs = sm + 1152 * 17;     // [1152]
    __shared__ float sred[256];
    __shared__ float sd[16];

    int bo = blockIdx.x;
    int t = threadIdx.x;

    const __half2* xg = (const __half2*)(g_xhat + (size_t)bo * 1152 * 16);
    for (int j = t; j < 1152 * 8; j += 256) {
        float2 f = __half22float2(xg[j]);
        int i = j >> 3, q = j & 7;
        float* dst = xs + i * 17 + q * 2;
        dst[0] = f.x; dst[1] = f.y;
    }
    const float* cg = g_c + (size_t)bo * 1152;
    for (int i = t; i < 1152; i += 256) cs[i] = cg[i];
    __syncthreads();

    int d = t & 15, g = t >> 4;
    float acc = 0.f;
    for (int i = g; i < 1152; i += 16)
        acc += cs[i] * xs[i * 17 + d];
    sred[t] = acc;
    __syncthreads();

    if (t < 16) {
        float s = 0.f;
#pragma unroll
        for (int gg = 0; gg < 16; gg++) s += sred[gg * 16 + t];
        sd[t] = s;
    }
    __syncthreads();

    if (t == 0) {
        float n2 = 0.f;
#pragma unroll
        for (int dd = 0; dd < 16; dd++) n2 += sd[dd] * sd[dd];
        float n = sqrtf(n2);
        float scale = n2 / (1.f + n2) / (n + 1e-8f);
        out[bo] = scale * n;
    }
}

// ---------------- launch ----------------
extern "C" void kernel_launch(void* const* d_in, const int* in_sizes, int n_in,
                              void* d_out, int out_size) {
    const float* x   = (const float*)d_in[0];
    const float* w1  = (const float*)d_in[1];
    const float* b1  = (const float*)d_in[2];
    const float* w2  = (const float*)d_in[3];
    const float* b2  = (const float*)d_in[4];
    const float* cw  = (const float*)d_in[5];
    float* out = (float*)d_out;

    const int CONV2_SMEM = 2 * BUFSZ;                    // 221184 B
    const int ROUTE_SMEM = (1152 * 17 + 1152) * 4;       // 82944 B
    const int W2_SMEM    = 256 * 81 * 4;                 // 82944 B
    const int XHAT_SMEM  = (16384 + 1024) * 4;           // 69632 B
    cudaFuncSetAttribute(conv2_mma, cudaFuncAttributeMaxDynamicSharedMemorySize, CONV2_SMEM);
    cudaFuncSetAttribute(convert_w2, cudaFuncAttributeMaxDynamicSharedMemorySize, W2_SMEM);
    cudaFuncSetAttribute(xhat_kernel, cudaFuncAttributeMaxDynamicSharedMemorySize, XHAT_SMEM);
    cudaFuncSetAttribute(routeAB_kernel<0>, cudaFuncAttributeMaxDynamicSharedMemorySize, ROUTE_SMEM);
    cudaFuncSetAttribute(routeAB_kernel<1>, cudaFuncAttributeMaxDynamicSharedMemorySize, ROUTE_SMEM);
    cudaFuncSetAttribute(routeFinal_kernel, cudaFuncAttributeMaxDynamicSharedMemorySize, ROUTE_SMEM);

    float *blog0, *blog1;
    cudaGetSymbolAddress((void**)&blog0, g_blog0);
    cudaGetSymbolAddress((void**)&blog1, g_blog1);

    conv1_kernel<<<dim3(512, 4), 256>>>(x, w1, b1);
    convert_w2<<<256, 256, W2_SMEM>>>(w2);
    conv2_mma<<<dim3(2, 72), 256, CONV2_SMEM>>>(b2);
    xhat_kernel<<<dim3(10, 9, 8), 256, XHAT_SMEM>>>(cw);

    routeAB_kernel<0><<<5120, 256, ROUTE_SMEM>>>(blog0, blog0);   // iter 0: uniform c
    softmax_c<<<(512 * 1152 + 255) / 256, 256>>>(blog0);
    routeAB_kernel<1><<<5120, 256, ROUTE_SMEM>>>(blog0, blog1);   // iter 1
    softmax_c<<<(512 * 1152 + 255) / 256, 256>>>(blog1);
    routeFinal_kernel<<<5120, 256, ROUTE_SMEM>>>(out);            // iter 2: lengths
}

// round 14
// speedup vs baseline: 3.2569x; 1.0276x over previous
#include <cuda_runtime.h>
#include <cuda_bf16.h>
#include <cuda_fp16.h>
#include <math.h>
#include <stdint.h>

// ---------------- scratch (static device globals; no runtime alloc) ----------------
__device__ __nv_bfloat16 g_h1_hi[(size_t)512 * 400 * 256];   // conv1 out hi, [b][pos][ci]
__device__ __nv_bfloat16 g_h1_lo[(size_t)512 * 400 * 256];   // conv1 out lo
__device__ __nv_bfloat16 g_w2_hi[81 * 256 * 256];            // pc_w hi, [kk][co][ci]
__device__ __nv_bfloat16 g_w2_lo[81 * 256 * 256];            // pc_w lo
__device__ float g_h2[512 * 9216];                           // conv2 out [b][i*8+k]
__device__ __half g_xhat[(size_t)512 * 10 * 1152 * 16];      // votes [b][o][i][d] (fp16)
__device__ float g_blog0[512 * 10 * 1152];                   // routing logits ping
__device__ float g_blog1[512 * 10 * 1152];                   // routing logits pong
__device__ float g_c[512 * 10 * 1152];                       // softmax coefficients

// ---------------- PTX helpers (sm_80-era; compile on plain sm_103 target) ----------------
__device__ __forceinline__ uint32_t smem_u32(const void* p) {
    uint32_t a;
    asm("{ .reg .u64 t; cvta.to.shared.u64 t, %1; cvt.u32.u64 %0, t; }" : "=r"(a) : "l"(p));
    return a;
}
__device__ __forceinline__ void ldm_x4(uint32_t* r, uint32_t addr) {
    asm volatile("ldmatrix.sync.aligned.m8n8.x4.shared.b16 {%0,%1,%2,%3}, [%4];"
                 : "=r"(r[0]), "=r"(r[1]), "=r"(r[2]), "=r"(r[3]) : "r"(addr));
}
__device__ __forceinline__ void mma_bf16(float* c, const uint32_t* a, const uint32_t* b) {
    asm volatile("mma.sync.aligned.m16n8k16.row.col.f32.bf16.bf16.f32 "
                 "{%0,%1,%2,%3}, {%4,%5,%6,%7}, {%8,%9}, {%0,%1,%2,%3};"
                 : "+f"(c[0]), "+f"(c[1]), "+f"(c[2]), "+f"(c[3])
                 : "r"(a[0]), "r"(a[1]), "r"(a[2]), "r"(a[3]), "r"(b[0]), "r"(b[1]));
}
__device__ __forceinline__ void cp16(uint32_t dst, const void* src) {
    asm volatile("cp.async.cg.shared.global [%0], [%1], 16;" :: "r"(dst), "l"(src));
}
__device__ __forceinline__ void cp_commit() { asm volatile("cp.async.commit_group;" ::: "memory"); }
__device__ __forceinline__ void cp_wait0()  { asm volatile("cp.async.wait_group 0;" ::: "memory"); }

// ---------------- conv1: [512,1,28,28] -> channel-last bf16 hi/lo, ReLU ----------------
__global__ __launch_bounds__(256) void conv1_kernel(const float* __restrict__ x,
                                                    const float* __restrict__ w1,
                                                    const float* __restrict__ b1) {
    __shared__ float xs[784];
    int b  = blockIdx.x;
    int oh0 = blockIdx.y * 5;
    int co = threadIdx.x;
    const float* xb = x + (size_t)b * 784;
    for (int idx = co; idx < 784; idx += 256) xs[idx] = xb[idx];
    __syncthreads();

    float bias = b1[co];
    const float* wco = w1 + co * 81;

    for (int oh = oh0; oh < oh0 + 5; oh++) {
        float acc[20];
#pragma unroll
        for (int ow = 0; ow < 20; ow++) acc[ow] = 0.f;

        for (int kh = 0; kh < 9; kh++) {
            float xr[28];
#pragma unroll
            for (int c = 0; c < 28; c++) xr[c] = xs[(oh + kh) * 28 + c];
#pragma unroll
            for (int kw = 0; kw < 9; kw++) {
                float w = __ldg(&wco[kh * 9 + kw]);
#pragma unroll
                for (int ow = 0; ow < 20; ow++) acc[ow] += w * xr[ow + kw];
            }
        }
        size_t base = (((size_t)b * 400) + oh * 20) * 256 + co;
#pragma unroll
        for (int ow = 0; ow < 20; ow++) {
            float v = acc[ow] + bias;
            v = v > 0.f ? v : 0.f;
            __nv_bfloat16 h = __float2bfloat16(v);
            __nv_bfloat16 l = __float2bfloat16(v - __bfloat162float(h));
            g_h1_hi[base + (size_t)ow * 256] = h;
            g_h1_lo[base + (size_t)ow * 256] = l;
        }
    }
}

// ---------------- pc_w convert (coalesced): [co][ci][k] fp32 -> [kk][co][ci] bf16 hi/lo ----------------
__global__ __launch_bounds__(256) void convert_w2(const float* __restrict__ pcw) {
    extern __shared__ float ws[];    // [ci][81]
    int co = blockIdx.x;
    int t = threadIdx.x;
    const float* src = pcw + (size_t)co * 256 * 81;
    for (int idx = t; idx < 256 * 81; idx += 256) ws[idx] = src[idx];
    __syncthreads();
    int ci = t;
    for (int k = 0; k < 81; k++) {
        float v = ws[ci * 81 + k];
        __nv_bfloat16 h = __float2bfloat16(v);
        __nv_bfloat16 l = __float2bfloat16(v - __bfloat162float(h));
        size_t o = ((size_t)k * 256 + co) * 256 + ci;
        g_w2_hi[o] = h;
        g_w2_lo[o] = l;
    }
}

// ---------------- conv2 via HMMA implicit GEMM, cp.async double-buffered ----------------
#define LDK 72
#define BUFSZ 110592
#define AHI 0
#define ALO 18432
#define BHI 36864
#define BLO 73728
#define NITER 324
__global__ __launch_bounds__(256, 1) void conv2_mma(const float* __restrict__ pcb) {
    extern __shared__ char smem[];
    uint32_t sb = smem_u32(smem);
    int tid = threadIdx.x;
    int wid = tid >> 5;
    int lane = tid & 31;
    int mtile = blockIdx.x;
    int ntile = blockIdx.y;

    int wm = wid & 3;
    int wn = wid >> 2;

    int seg = tid & 7;
    int rbase = tid >> 3;
    uint32_t adst[4];
    uint32_t aoff[4];
#pragma unroll
    for (int j = 0; j < 4; j++) {
        int row = rbase + j * 32;
        adst[j] = (uint32_t)(row * LDK + seg * 8) * 2;
        aoff[j] = (uint32_t)((mtile * 128 + row) * 256 + seg * 8);
    }
    uint32_t bdst[8];
    size_t gb[8];
#pragma unroll
    for (int j = 0; j < 8; j++) {
        int row = rbase + j * 32;
        bdst[j] = (uint32_t)(row * LDK + seg * 8) * 2;
        int p = ntile * 256 + row;
        int b = p / 36;
        int s = p - b * 36;
        int oh = s / 6, ow = s - oh * 6;
        gb[j] = ((size_t)b * 400 + oh * 40 + ow * 2) * 256 + seg * 8;
    }

    float acc[2][16][4];
#pragma unroll
    for (int mt = 0; mt < 2; mt++)
#pragma unroll
        for (int nt = 0; nt < 16; nt++)
#pragma unroll
            for (int j = 0; j < 4; j++) acc[mt][nt][j] = 0.f;

    int rowA = lane & 15;
    int kgA  = (lane >> 4) << 3;
    int rowB = ((lane >> 4) << 3) + (lane & 7);
    int kgB  = ((lane >> 3) & 1) << 3;

#define STAGE(IT, BSEL) do {                                                        \
        int _it = (IT);                                                             \
        int _cb = (_it / 81) << 6;                                                  \
        int _kk = _it - (_it / 81) * 81;                                            \
        int _kh = _kk / 9, _kw = _kk - _kh * 9;                                     \
        uint32_t _bu = sb + (BSEL) * BUFSZ;                                         \
        size_t _abase = ((size_t)_kk * 256) * 256 + _cb;                            \
        size_t _boff = (size_t)(_kh * 20 + _kw) * 256 + _cb;                        \
        _Pragma("unroll")                                                           \
        for (int j = 0; j < 4; j++) {                                               \
            size_t _s = _abase + aoff[j];                                           \
            cp16(_bu + AHI + adst[j], (const char*)g_w2_hi + _s * 2);               \
            cp16(_bu + ALO + adst[j], (const char*)g_w2_lo + _s * 2);               \
        }                                                                           \
        _Pragma("unroll")                                                           \
        for (int j = 0; j < 8; j++) {                                               \
            size_t _s = gb[j] + _boff;                                              \
            cp16(_bu + BHI + bdst[j], (const char*)g_h1_hi + _s * 2);               \
            cp16(_bu + BLO + bdst[j], (const char*)g_h1_lo + _s * 2);               \
        }                                                                           \
    } while (0)

    STAGE(0, 0);
    cp_commit();
    cp_wait0();
    __syncthreads();

    for (int it = 0; it < NITER; it++) {
        if (it + 1 < NITER) { STAGE(it + 1, (it + 1) & 1); cp_commit(); }

        uint32_t bu = sb + (it & 1) * BUFSZ;
#pragma unroll
        for (int ks = 0; ks < 4; ks++) {
            int k0 = ks * 16;
            uint32_t ahi[2][4], alo[2][4];
#pragma unroll
            for (int mt = 0; mt < 2; mt++) {
                uint32_t arow = (uint32_t)((wm * 32 + mt * 16 + rowA) * LDK + k0 + kgA) * 2;
                ldm_x4(ahi[mt], bu + AHI + arow);
                ldm_x4(alo[mt], bu + ALO + arow);
            }
#pragma unroll
            for (int nh = 0; nh < 4; nh++) {
                uint32_t bhi[4][2], blo[4][2];
#pragma unroll
                for (int nq = 0; nq < 2; nq++) {
                    uint32_t brow = (uint32_t)((wn * 128 + nh * 32 + nq * 16 + rowB) * LDK + k0 + kgB) * 2;
                    uint32_t t4[4];
                    ldm_x4(t4, bu + BHI + brow);
                    bhi[2 * nq][0] = t4[0]; bhi[2 * nq][1] = t4[1];
                    bhi[2 * nq + 1][0] = t4[2]; bhi[2 * nq + 1][1] = t4[3];
                    ldm_x4(t4, bu + BLO + brow);
                    blo[2 * nq][0] = t4[0]; blo[2 * nq][1] = t4[1];
                    blo[2 * nq + 1][0] = t4[2]; blo[2 * nq + 1][1] = t4[3];
                }
#pragma unroll
                for (int mt = 0; mt < 2; mt++)
#pragma unroll
                    for (int nq = 0; nq < 4; nq++) {
                        int nt = nh * 4 + nq;
                        mma_bf16(acc[mt][nt], ahi[mt], bhi[nq]);
                        mma_bf16(acc[mt][nt], ahi[mt], blo[nq]);
                        mma_bf16(acc[mt][nt], alo[mt], bhi[nq]);
                    }
            }
        }
        if (it + 1 < NITER) cp_wait0();
        __syncthreads();
    }

    int r0 = lane >> 2, cp = lane & 3;
#pragma unroll
    for (int mt = 0; mt < 2; mt++) {
#pragma unroll
        for (int half = 0; half < 2; half++) {
            int m = wm * 32 + mt * 16 + r0 + half * 8;
            int co = mtile * 128 + m;
            float bias = pcb[co];
#pragma unroll
            for (int nt = 0; nt < 16; nt++) {
#pragma unroll
                for (int e = 0; e < 2; e++) {
                    int p = ntile * 256 + wn * 128 + nt * 8 + 2 * cp + e;
                    int b = p / 36;
                    int s = p - b * 36;
                    g_h2[(size_t)b * 9216 + co * 36 + s] = acc[mt][nt][half * 2 + e] + bias;
                }
            }
        }
    }
}

// ---------------- votes + fused squash: fp16 weights in smem, d-pair threads ----------------
// wt: 4 planes (k-pairs) of half2[2048] indexed il*16+d; us: squashed slab fp32.
// grid (10 o, 9 ic, 16 bc) -> 32 b per block; o fastest for h2 L2 reuse.
__global__ __launch_bounds__(256) void xhat_kernel(const float* __restrict__ cw) {
    extern __shared__ float xsm[];
    __half2* wt = (__half2*)xsm;            // 4 * 2048 half2 = 32768 B
    float* us = xsm + 8192;                 // 1024 floats

    int o  = blockIdx.x;
    int ic = blockIdx.y;
    int bc = blockIdx.z;
    int t  = threadIdx.x;

    // stage caps_w tile -> fp16 planes: src float4 j covers (il, d, k0..k0+3), k0 in {0,4}
    const float4* src = (const float4*)(cw + ((size_t)o * 1152 + ic * 128) * 128);
    for (int j = t; j < 4096; j += 256) {
        float4 v = src[j];
        int fo = j * 4;
        int il = fo >> 7, rem = fo & 127;
        int d = rem >> 3, k0 = rem & 7;              // k0 = 0 or 4
        int p0 = k0 >> 1;                            // plane 0 or 2
        wt[p0 * 2048 + il * 16 + d]       = __floats2half2_rn(v.x, v.y);
        wt[(p0 + 1) * 2048 + il * 16 + d] = __floats2half2_rn(v.z, v.w);
    }
    __syncthreads();

    int d8 = t & 7;          // d-pair: d = 2*d8, 2*d8+1
    int tr = t >> 3;         // 0..31

    for (int bl = 0; bl < 32; bl++) {
        int b = bc * 32 + bl;
        const float4* hp = (const float4*)(g_h2 + (size_t)b * 9216 + (size_t)ic * 1024);
        __syncthreads();
        {
            float4 v = hp[t];
            float dp = v.x * v.x + v.y * v.y + v.z * v.z + v.w * v.w;
            float n2 = dp + __shfl_xor_sync(0xffffffffu, dp, 1);
            float n = sqrtf(n2);
            float scale = n2 / (1.f + n2) / (n + 1e-8f);
            v.x *= scale; v.y *= scale; v.z *= scale; v.w *= scale;
            *(float4*)(us + t * 4) = v;
        }
        __syncthreads();

        __half2* xout = (__half2*)(g_xhat + (((size_t)(b * 10 + o) * 1152) + ic * 128) * 16);
#pragma unroll
        for (int isub = 0; isub < 4; isub++) {
            int il = isub * 32 + tr;
            int wi = il * 16 + 2 * d8;
            // per plane: two consecutive half2 (d, d+1) -> one LDS.64
            float4 u0 = *(const float4*)(us + il * 8);
            float4 u1 = *(const float4*)(us + il * 8 + 4);
            float a0 = 0.f, a1 = 0.f;
#pragma unroll
            for (int p = 0; p < 4; p++) {
                __half2 h0 = wt[p * 2048 + wi];
                __half2 h1 = wt[p * 2048 + wi + 1];
                float2 f0 = __half22float2(h0);     // (k=2p, 2p+1) for d
                float2 f1 = __half22float2(h1);     // (k=2p, 2p+1) for d+1
                float uk0 = (p == 0) ? u0.x : (p == 1) ? u0.z : (p == 2) ? u1.x : u1.z;
                float uk1 = (p == 0) ? u0.y : (p == 1) ? u0.w : (p == 2) ? u1.y : u1.w;
                a0 += f0.x * uk0 + f0.y * uk1;
                a1 += f1.x * uk0 + f1.y * uk1;
            }
            xout[il * 8 + d8] = __floats2half2_rn(a0, a1);
        }
    }
}

// ---------------- softmax over output caps ----------------
__global__ __launch_bounds__(256) void softmax_c(const float* __restrict__ blog) {
    int idx = blockIdx.x * 256 + threadIdx.x;
    if (idx >= 512 * 1152) return;
    int b = idx / 1152, i = idx - b * 1152;
    const float* blb = blog + (size_t)b * 10 * 1152 + i;
    float vals[10];
    float m = -1e30f;
#pragma unroll
    for (int o = 0; o < 10; o++) {
        vals[o] = blb[(size_t)o * 1152];
        m = fmaxf(m, vals[o]);
    }
    float sum = 0.f;
#pragma unroll
    for (int o = 0; o < 10; o++) { vals[o] = expf(vals[o] - m); sum += vals[o]; }
    float inv = 1.f / sum;
    float* cb = g_c + (size_t)b * 10 * 1152 + i;
#pragma unroll
    for (int o = 0; o < 10; o++) cb[(size_t)o * 1152] = vals[o] * inv;
}

// ---------------- fused routing A+B (fp16 x_hat) ----------------
template <int MODE>
__global__ __launch_bounds__(256) void routeAB_kernel(const float* __restrict__ blin_g,
                                                      float* __restrict__ blout_g) {
    extern __shared__ float sm[];
    float* xs = sm;                 // [1152][17]
    float* cs = sm + 1152 * 17;     // [1152]
    __shared__ float sred[256];
    __shared__ float sd[16];
    __shared__ float sscale;

    int bo = blockIdx.x;
    int t = threadIdx.x;

    const __half2* xg = (const __half2*)(g_xhat + (size_t)bo * 1152 * 16);
    for (int j = t; j < 1152 * 8; j += 256) {
        float2 f = __half22float2(xg[j]);
        int i = j >> 3, q = j & 7;
        float* dst = xs + i * 17 + q * 2;
        dst[0] = f.x; dst[1] = f.y;
    }

    if (MODE == 1) {
        const float* cg = g_c + (size_t)bo * 1152;
        for (int i = t; i < 1152; i += 256) cs[i] = cg[i];
    } else {
        for (int i = t; i < 1152; i += 256) cs[i] = 0.1f;
    }
    __syncthreads();

    int d = t & 15, g = t >> 4;
    float acc = 0.f;
    for (int i = g; i < 1152; i += 16)
        acc += cs[i] * xs[i * 17 + d];
    sred[t] = acc;
    __syncthreads();

    if (t < 16) {
        float s = 0.f;
#pragma unroll
        for (int gg = 0; gg < 16; gg++) s += sred[gg * 16 + t];
        sd[t] = s;
    }
    __syncthreads();

    if (t == 0) {
        float n2 = 0.f;
#pragma unroll
        for (int dd = 0; dd < 16; dd++) n2 += sd[dd] * sd[dd];
        float n = sqrtf(n2);
        sscale = n2 / (1.f + n2) / (n + 1e-8f);
    }
    __syncthreads();

    float scale = sscale;
    const float* blin = blin_g + (size_t)bo * 1152;
    float* blout = blout_g + (size_t)bo * 1152;
    for (int i = t; i < 1152; i += 256) {
        float dot = 0.f;
        const float* xr = xs + i * 17;
#pragma unroll
        for (int dd = 0; dd < 16; dd++) dot += sd[dd] * xr[dd];
        dot *= scale;
        blout[i] = (MODE == 1) ? (blin[i] + dot) : dot;
    }
}

// ---------------- final routing pass: c -> capsule lengths (fp16 x_hat) ----------------
__global__ __launch_bounds__(256) void routeFinal_kernel(float* __restrict__ out) {
    extern __shared__ float sm[];
    float* xs = sm;                 // [1152][17]
    float* cs = sm + 1152 * 17;     // [1152]
    __shared__ float sred[256];
    __shared__ float sd[16];

    int bo = blockIdx.x;
    int t = threadIdx.x;

    const __half2* xg = (const __half2*)(g_xhat + (size_t)bo * 1152 * 16);
    for (int j = t; j < 1152 * 8; j += 256) {
        float2 f = __half22float2(xg[j]);
        int i = j >> 3, q = j & 7;
        float* dst = xs + i * 17 + q * 2;
        dst[0] = f.x; dst[1] = f.y;
    }
    const float* cg = g_c + (size_t)bo * 1152;
    for (int i = t; i < 1152; i += 256) cs[i] = cg[i];
    __syncthreads();

    int d = t & 15, g = t >> 4;
    float acc = 0.f;
    for (int i = g; i < 1152; i += 16)
        acc += cs[i] * xs[i * 17 + d];
    sred[t] = acc;
    __syncthreads();

    if (t < 16) {
        float s = 0.f;
#pragma unroll
        for (int gg = 0; gg < 16; gg++) s += sred[gg * 16 + t];
        sd[t] = s;
    }
    __syncthreads();

    if (t == 0) {
        float n2 = 0.f;
#pragma unroll
        for (int dd = 0; dd < 16; dd++) n2 += sd[dd] * sd[dd];
        float n = sqrtf(n2);
        float scale = n2 / (1.f + n2) / (n + 1e-8f);
        out[bo] = scale * n;
    }
}

// ---------------- launch ----------------
extern "C" void kernel_launch(void* const* d_in, const int* in_sizes, int n_in,
                              void* d_out, int out_size) {
    const float* x   = (const float*)d_in[0];
    const float* w1  = (const float*)d_in[1];
    const float* b1  = (const float*)d_in[2];
    const float* w2  = (const float*)d_in[3];
    const float* b2  = (const float*)d_in[4];
    const float* cw  = (const float*)d_in[5];
    float* out = (float*)d_out;

    const int CONV2_SMEM = 2 * BUFSZ;                    // 221184 B
    const int ROUTE_SMEM = (1152 * 17 + 1152) * 4;       // 82944 B
    const int W2_SMEM    = 256 * 81 * 4;                 // 82944 B
    const int XHAT_SMEM  = 32768 + 4096;                 // 36864 B
    cudaFuncSetAttribute(conv2_mma, cudaFuncAttributeMaxDynamicSharedMemorySize, CONV2_SMEM);
    cudaFuncSetAttribute(convert_w2, cudaFuncAttributeMaxDynamicSharedMemorySize, W2_SMEM);
    cudaFuncSetAttribute(xhat_kernel, cudaFuncAttributeMaxDynamicSharedMemorySize, XHAT_SMEM);
    cudaFuncSetAttribute(routeAB_kernel<0>, cudaFuncAttributeMaxDynamicSharedMemorySize, ROUTE_SMEM);
    cudaFuncSetAttribute(routeAB_kernel<1>, cudaFuncAttributeMaxDynamicSharedMemorySize, ROUTE_SMEM);
    cudaFuncSetAttribute(routeFinal_kernel, cudaFuncAttributeMaxDynamicSharedMemorySize, ROUTE_SMEM);

    float *blog0, *blog1;
    cudaGetSymbolAddress((void**)&blog0, g_blog0);
    cudaGetSymbolAddress((void**)&blog1, g_blog1);

    conv1_kernel<<<dim3(512, 4), 256>>>(x, w1, b1);
    convert_w2<<<256, 256, W2_SMEM>>>(w2);
    conv2_mma<<<dim3(2, 72), 256, CONV2_SMEM>>>(b2);
    xhat_kernel<<<dim3(10, 9, 16), 256, XHAT_SMEM>>>(cw);

    routeAB_kernel<0><<<5120, 256, ROUTE_SMEM>>>(blog0, blog0);   // iter 0: uniform c
    softmax_c<<<(512 * 1152 + 255) / 256, 256>>>(blog0);
    routeAB_kernel<1><<<5120, 256, ROUTE_SMEM>>>(blog0, blog1);   // iter 1
    softmax_c<<<(512 * 1152 + 255) / 256, 256>>>(blog1);
    routeFinal_kernel<<<5120, 256, ROUTE_SMEM>>>(out);            // iter 2: lengths
}

// round 15
// speedup vs baseline: 3.2882x; 1.0096x over previous
#include <cuda_runtime.h>
#include <cuda_bf16.h>
#include <cuda_fp16.h>
#include <math.h>
#include <stdint.h>

// ---------------- scratch (static device globals; no runtime alloc) ----------------
__device__ __nv_bfloat16 g_h1_hi[(size_t)512 * 400 * 256];   // conv1 out hi, [b][pos][ci]
__device__ __nv_bfloat16 g_h1_lo[(size_t)512 * 400 * 256];   // conv1 out lo
__device__ __nv_bfloat16 g_w2_hi[81 * 256 * 256];            // pc_w hi, [kk][co][ci]
__device__ __nv_bfloat16 g_w2_lo[81 * 256 * 256];            // pc_w lo
__device__ float g_h2[512 * 9216];                           // conv2 out [b][i*8+k]
__device__ __half g_xhat[(size_t)512 * 10 * 1152 * 16];      // votes [b][o][i][d] (fp16)
__device__ float g_blog0[512 * 10 * 1152];                   // routing logits ping
__device__ float g_blog1[512 * 10 * 1152];                   // routing logits pong
__device__ float g_c[512 * 10 * 1152];                       // softmax coefficients

#define XS_LD 20   // smem row stride (floats) for x_hat tiles in routing kernels

// ---------------- PTX helpers (sm_80-era; compile on plain sm_103 target) ----------------
__device__ __forceinline__ uint32_t smem_u32(const void* p) {
    uint32_t a;
    asm("{ .reg .u64 t; cvta.to.shared.u64 t, %1; cvt.u32.u64 %0, t; }" : "=r"(a) : "l"(p));
    return a;
}
__device__ __forceinline__ void ldm_x4(uint32_t* r, uint32_t addr) {
    asm volatile("ldmatrix.sync.aligned.m8n8.x4.shared.b16 {%0,%1,%2,%3}, [%4];"
                 : "=r"(r[0]), "=r"(r[1]), "=r"(r[2]), "=r"(r[3]) : "r"(addr));
}
__device__ __forceinline__ void mma_bf16(float* c, const uint32_t* a, const uint32_t* b) {
    asm volatile("mma.sync.aligned.m16n8k16.row.col.f32.bf16.bf16.f32 "
                 "{%0,%1,%2,%3}, {%4,%5,%6,%7}, {%8,%9}, {%0,%1,%2,%3};"
                 : "+f"(c[0]), "+f"(c[1]), "+f"(c[2]), "+f"(c[3])
                 : "r"(a[0]), "r"(a[1]), "r"(a[2]), "r"(a[3]), "r"(b[0]), "r"(b[1]));
}
__device__ __forceinline__ void cp16(uint32_t dst, const void* src) {
    asm volatile("cp.async.cg.shared.global [%0], [%1], 16;" :: "r"(dst), "l"(src));
}
__device__ __forceinline__ void cp_commit() { asm volatile("cp.async.commit_group;" ::: "memory"); }
__device__ __forceinline__ void cp_wait0()  { asm volatile("cp.async.wait_group 0;" ::: "memory"); }

// ---------------- conv1: [512,1,28,28] -> channel-last bf16 hi/lo, ReLU ----------------
__global__ __launch_bounds__(256) void conv1_kernel(const float* __restrict__ x,
                                                    const float* __restrict__ w1,
                                                    const float* __restrict__ b1) {
    __shared__ float xs[784];
    int b  = blockIdx.x;
    int oh0 = blockIdx.y * 5;
    int co = threadIdx.x;
    const float* xb = x + (size_t)b * 784;
    for (int idx = co; idx < 784; idx += 256) xs[idx] = xb[idx];
    __syncthreads();

    float bias = b1[co];
    const float* wco = w1 + co * 81;

    for (int oh = oh0; oh < oh0 + 5; oh++) {
        float acc[20];
#pragma unroll
        for (int ow = 0; ow < 20; ow++) acc[ow] = 0.f;

        for (int kh = 0; kh < 9; kh++) {
            float xr[28];
#pragma unroll
            for (int c = 0; c < 28; c++) xr[c] = xs[(oh + kh) * 28 + c];
#pragma unroll
            for (int kw = 0; kw < 9; kw++) {
                float w = __ldg(&wco[kh * 9 + kw]);
#pragma unroll
                for (int ow = 0; ow < 20; ow++) acc[ow] += w * xr[ow + kw];
            }
        }
        size_t base = (((size_t)b * 400) + oh * 20) * 256 + co;
#pragma unroll
        for (int ow = 0; ow < 20; ow++) {
            float v = acc[ow] + bias;
            v = v > 0.f ? v : 0.f;
            __nv_bfloat16 h = __float2bfloat16(v);
            __nv_bfloat16 l = __float2bfloat16(v - __bfloat162float(h));
            g_h1_hi[base + (size_t)ow * 256] = h;
            g_h1_lo[base + (size_t)ow * 256] = l;
        }
    }
}

// ---------------- pc_w convert (coalesced): [co][ci][k] fp32 -> [kk][co][ci] bf16 hi/lo ----------------
__global__ __launch_bounds__(256) void convert_w2(const float* __restrict__ pcw) {
    extern __shared__ float ws[];    // [ci][81]
    int co = blockIdx.x;
    int t = threadIdx.x;
    const float* src = pcw + (size_t)co * 256 * 81;
    for (int idx = t; idx < 256 * 81; idx += 256) ws[idx] = src[idx];
    __syncthreads();
    int ci = t;
    for (int k = 0; k < 81; k++) {
        float v = ws[ci * 81 + k];
        __nv_bfloat16 h = __float2bfloat16(v);
        __nv_bfloat16 l = __float2bfloat16(v - __bfloat162float(h));
        size_t o = ((size_t)k * 256 + co) * 256 + ci;
        g_w2_hi[o] = h;
        g_w2_lo[o] = l;
    }
}

// ---------------- conv2 via HMMA implicit GEMM, cp.async double-buffered ----------------
#define LDK 72
#define BUFSZ 110592
#define AHI 0
#define ALO 18432
#define BHI 36864
#define BLO 73728
#define NITER 324
__global__ __launch_bounds__(256, 1) void conv2_mma(const float* __restrict__ pcb) {
    extern __shared__ char smem[];
    uint32_t sb = smem_u32(smem);
    int tid = threadIdx.x;
    int wid = tid >> 5;
    int lane = tid & 31;
    int mtile = blockIdx.x;
    int ntile = blockIdx.y;

    int wm = wid & 3;
    int wn = wid >> 2;

    int seg = tid & 7;
    int rbase = tid >> 3;
    uint32_t adst[4];
    uint32_t aoff[4];
#pragma unroll
    for (int j = 0; j < 4; j++) {
        int row = rbase + j * 32;
        adst[j] = (uint32_t)(row * LDK + seg * 8) * 2;
        aoff[j] = (uint32_t)((mtile * 128 + row) * 256 + seg * 8);
    }
    uint32_t bdst[8];
    size_t gb[8];
#pragma unroll
    for (int j = 0; j < 8; j++) {
        int row = rbase + j * 32;
        bdst[j] = (uint32_t)(row * LDK + seg * 8) * 2;
        int p = ntile * 256 + row;
        int b = p / 36;
        int s = p - b * 36;
        int oh = s / 6, ow = s - oh * 6;
        gb[j] = ((size_t)b * 400 + oh * 40 + ow * 2) * 256 + seg * 8;
    }

    float acc[2][16][4];
#pragma unroll
    for (int mt = 0; mt < 2; mt++)
#pragma unroll
        for (int nt = 0; nt < 16; nt++)
#pragma unroll
            for (int j = 0; j < 4; j++) acc[mt][nt][j] = 0.f;

    int rowA = lane & 15;
    int kgA  = (lane >> 4) << 3;
    int rowB = ((lane >> 4) << 3) + (lane & 7);
    int kgB  = ((lane >> 3) & 1) << 3;

#define STAGE(IT, BSEL) do {                                                        \
        int _it = (IT);                                                             \
        int _cb = (_it / 81) << 6;                                                  \
        int _kk = _it - (_it / 81) * 81;                                            \
        int _kh = _kk / 9, _kw = _kk - _kh * 9;                                     \
        uint32_t _bu = sb + (BSEL) * BUFSZ;                                         \
        size_t _abase = ((size_t)_kk * 256) * 256 + _cb;                            \
        size_t _boff = (size_t)(_kh * 20 + _kw) * 256 + _cb;                        \
        _Pragma("unroll")                                                           \
        for (int j = 0; j < 4; j++) {                                               \
            size_t _s = _abase + aoff[j];                                           \
            cp16(_bu + AHI + adst[j], (const char*)g_w2_hi + _s * 2);               \
            cp16(_bu + ALO + adst[j], (const char*)g_w2_lo + _s * 2);               \
        }                                                                           \
        _Pragma("unroll")                                                           \
        for (int j = 0; j < 8; j++) {                                               \
            size_t _s = gb[j] + _boff;                                              \
            cp16(_bu + BHI + bdst[j], (const char*)g_h1_hi + _s * 2);               \
            cp16(_bu + BLO + bdst[j], (const char*)g_h1_lo + _s * 2);               \
        }                                                                           \
    } while (0)

    STAGE(0, 0);
    cp_commit();
    cp_wait0();
    __syncthreads();

    for (int it = 0; it < NITER; it++) {
        if (it + 1 < NITER) { STAGE(it + 1, (it + 1) & 1); cp_commit(); }

        uint32_t bu = sb + (it & 1) * BUFSZ;
#pragma unroll
        for (int ks = 0; ks < 4; ks++) {
            int k0 = ks * 16;
            uint32_t ahi[2][4], alo[2][4];
#pragma unroll
            for (int mt = 0; mt < 2; mt++) {
                uint32_t arow = (uint32_t)((wm * 32 + mt * 16 + rowA) * LDK + k0 + kgA) * 2;
                ldm_x4(ahi[mt], bu + AHI + arow);
                ldm_x4(alo[mt], bu + ALO + arow);
            }
#pragma unroll
            for (int nh = 0; nh < 4; nh++) {
                uint32_t bhi[4][2], blo[4][2];
#pragma unroll
                for (int nq = 0; nq < 2; nq++) {
                    uint32_t brow = (uint32_t)((wn * 128 + nh * 32 + nq * 16 + rowB) * LDK + k0 + kgB) * 2;
                    uint32_t t4[4];
                    ldm_x4(t4, bu + BHI + brow);
                    bhi[2 * nq][0] = t4[0]; bhi[2 * nq][1] = t4[1];
                    bhi[2 * nq + 1][0] = t4[2]; bhi[2 * nq + 1][1] = t4[3];
                    ldm_x4(t4, bu + BLO + brow);
                    blo[2 * nq][0] = t4[0]; blo[2 * nq][1] = t4[1];
                    blo[2 * nq + 1][0] = t4[2]; blo[2 * nq + 1][1] = t4[3];
                }
#pragma unroll
                for (int mt = 0; mt < 2; mt++)
#pragma unroll
                    for (int nq = 0; nq < 4; nq++) {
                        int nt = nh * 4 + nq;
                        mma_bf16(acc[mt][nt], ahi[mt], bhi[nq]);
                        mma_bf16(acc[mt][nt], ahi[mt], blo[nq]);
                        mma_bf16(acc[mt][nt], alo[mt], bhi[nq]);
                    }
            }
        }
        if (it + 1 < NITER) cp_wait0();
        __syncthreads();
    }

    int r0 = lane >> 2, cp = lane & 3;
#pragma unroll
    for (int mt = 0; mt < 2; mt++) {
#pragma unroll
        for (int half = 0; half < 2; half++) {
            int m = wm * 32 + mt * 16 + r0 + half * 8;
            int co = mtile * 128 + m;
            float bias = pcb[co];
#pragma unroll
            for (int nt = 0; nt < 16; nt++) {
#pragma unroll
                for (int e = 0; e < 2; e++) {
                    int p = ntile * 256 + wn * 128 + nt * 8 + 2 * cp + e;
                    int b = p / 36;
                    int s = p - b * 36;
                    g_h2[(size_t)b * 9216 + co * 36 + s] = acc[mt][nt][half * 2 + e] + bias;
                }
            }
        }
    }
}

// ---------------- votes + fused squash: fp16 weights, d-pair threads, LDS.64 weight loads ----------------
__global__ __launch_bounds__(256) void xhat_kernel(const float* __restrict__ cw) {
    extern __shared__ float xsm[];
    __half2* wt = (__half2*)xsm;            // 4 * 2048 half2 = 32768 B
    float* us = xsm + 8192;                 // 1024 floats

    int o  = blockIdx.x;
    int ic = blockIdx.y;
    int bc = blockIdx.z;
    int t  = threadIdx.x;

    const float4* src = (const float4*)(cw + ((size_t)o * 1152 + ic * 128) * 128);
    for (int j = t; j < 4096; j += 256) {
        float4 v = src[j];
        int fo = j * 4;
        int il = fo >> 7, rem = fo & 127;
        int d = rem >> 3, k0 = rem & 7;
        int p0 = k0 >> 1;
        wt[p0 * 2048 + il * 16 + d]       = __floats2half2_rn(v.x, v.y);
        wt[(p0 + 1) * 2048 + il * 16 + d] = __floats2half2_rn(v.z, v.w);
    }
    __syncthreads();

    int d8 = t & 7;
    int tr = t >> 3;

    for (int bl = 0; bl < 32; bl++) {
        int b = bc * 32 + bl;
        const float4* hp = (const float4*)(g_h2 + (size_t)b * 9216 + (size_t)ic * 1024);
        __syncthreads();
        {
            float4 v = hp[t];
            float dp = v.x * v.x + v.y * v.y + v.z * v.z + v.w * v.w;
            float n2 = dp + __shfl_xor_sync(0xffffffffu, dp, 1);
            float n = sqrtf(n2);
            float scale = n2 / (1.f + n2) / (n + 1e-8f);
            v.x *= scale; v.y *= scale; v.z *= scale; v.w *= scale;
            *(float4*)(us + t * 4) = v;
        }
        __syncthreads();

        __half2* xout = (__half2*)(g_xhat + (((size_t)(b * 10 + o) * 1152) + ic * 128) * 16);
#pragma unroll
        for (int isub = 0; isub < 4; isub++) {
            int il = isub * 32 + tr;
            int wi = il * 16 + 2 * d8;          // even -> 8B aligned
            float4 u0 = *(const float4*)(us + il * 8);
            float4 u1 = *(const float4*)(us + il * 8 + 4);
            float a0 = 0.f, a1 = 0.f;
#pragma unroll
            for (int p = 0; p < 4; p++) {
                uint2 hw = *(const uint2*)(wt + p * 2048 + wi);   // LDS.64: (d, d+1) half2s
                float2 f0 = __half22float2(*(const __half2*)&hw.x);
                float2 f1 = __half22float2(*(const __half2*)&hw.y);
                float uk0 = (p == 0) ? u0.x : (p == 1) ? u0.z : (p == 2) ? u1.x : u1.z;
                float uk1 = (p == 0) ? u0.y : (p == 1) ? u0.w : (p == 2) ? u1.y : u1.w;
                a0 += f0.x * uk0 + f0.y * uk1;
                a1 += f1.x * uk0 + f1.y * uk1;
            }
            xout[il * 8 + d8] = __floats2half2_rn(a0, a1);
        }
    }
}

// ---------------- softmax over output caps ----------------
__global__ __launch_bounds__(256) void softmax_c(const float* __restrict__ blog) {
    int idx = blockIdx.x * 256 + threadIdx.x;
    if (idx >= 512 * 1152) return;
    int b = idx / 1152, i = idx - b * 1152;
    const float* blb = blog + (size_t)b * 10 * 1152 + i;
    float vals[10];
    float m = -1e30f;
#pragma unroll
    for (int o = 0; o < 10; o++) {
        vals[o] = blb[(size_t)o * 1152];
        m = fmaxf(m, vals[o]);
    }
    float sum = 0.f;
#pragma unroll
    for (int o = 0; o < 10; o++) { vals[o] = expf(vals[o] - m); sum += vals[o]; }
    float inv = 1.f / sum;
    float* cb = g_c + (size_t)b * 10 * 1152 + i;
#pragma unroll
    for (int o = 0; o < 10; o++) cb[(size_t)o * 1152] = vals[o] * inv;
}

// ---------------- fused routing A+B (fp16 x_hat, stride-20 smem, float4 dot pass) ----------------
template <int MODE>
__global__ __launch_bounds__(256) void routeAB_kernel(const float* __restrict__ blin_g,
                                                      float* __restrict__ blout_g) {
    extern __shared__ float sm[];
    float* xs = sm;                    // [1152][XS_LD]
    float* cs = sm + 1152 * XS_LD;     // [1152]
    __shared__ float sred[256];
    __shared__ float sd[16];
    __shared__ float sscale;

    int bo = blockIdx.x;
    int t = threadIdx.x;

    const __half2* xg = (const __half2*)(g_xhat + (size_t)bo * 1152 * 16);
    for (int j = t; j < 1152 * 8; j += 256) {
        float2 f = __half22float2(xg[j]);
        int i = j >> 3, q = j & 7;
        float* dst = xs + i * XS_LD + q * 2;
        dst[0] = f.x; dst[1] = f.y;
    }

    if (MODE == 1) {
        const float* cg = g_c + (size_t)bo * 1152;
        for (int i = t; i < 1152; i += 256) cs[i] = cg[i];
    } else {
        for (int i = t; i < 1152; i += 256) cs[i] = 0.1f;
    }
    __syncthreads();

    int d = t & 15, g = t >> 4;
    float acc = 0.f;
    for (int i = g; i < 1152; i += 16)
        acc += cs[i] * xs[i * XS_LD + d];
    sred[t] = acc;
    __syncthreads();

    if (t < 16) {
        float s = 0.f;
#pragma unroll
        for (int gg = 0; gg < 16; gg++) s += sred[gg * 16 + t];
        sd[t] = s;
    }
    __syncthreads();

    if (t == 0) {
        float n2 = 0.f;
#pragma unroll
        for (int dd = 0; dd < 16; dd++) n2 += sd[dd] * sd[dd];
        float n = sqrtf(n2);
        sscale = n2 / (1.f + n2) / (n + 1e-8f);
    }
    __syncthreads();

    float scale = sscale;
    float v0 = sd[0], v1 = sd[1], v2 = sd[2], v3 = sd[3];
    float v4 = sd[4], v5 = sd[5], v6 = sd[6], v7 = sd[7];
    float v8 = sd[8], v9 = sd[9], v10 = sd[10], v11 = sd[11];
    float v12 = sd[12], v13 = sd[13], v14 = sd[14], v15 = sd[15];
    const float* blin = blin_g + (size_t)bo * 1152;
    float* blout = blout_g + (size_t)bo * 1152;
    for (int i = t; i < 1152; i += 256) {
        const float* xr = xs + i * XS_LD;
        float4 xa = *(const float4*)(xr);
        float4 xb = *(const float4*)(xr + 4);
        float4 xc = *(const float4*)(xr + 8);
        float4 xd = *(const float4*)(xr + 12);
        float dot = xa.x * v0 + xa.y * v1 + xa.z * v2 + xa.w * v3
                  + xb.x * v4 + xb.y * v5 + xb.z * v6 + xb.w * v7
                  + xc.x * v8 + xc.y * v9 + xc.z * v10 + xc.w * v11
                  + xd.x * v12 + xd.y * v13 + xd.z * v14 + xd.w * v15;
        dot *= scale;
        blout[i] = (MODE == 1) ? (blin[i] + dot) : dot;
    }
}

// ---------------- final routing pass: c -> capsule lengths (fp16 x_hat) ----------------
__global__ __launch_bounds__(256) void routeFinal_kernel(float* __restrict__ out) {
    extern __shared__ float sm[];
    float* xs = sm;                    // [1152][XS_LD]
    float* cs = sm + 1152 * XS_LD;     // [1152]
    __shared__ float sred[256];
    __shared__ float sd[16];

    int bo = blockIdx.x;
    int t = threadIdx.x;

    const __half2* xg = (const __half2*)(g_xhat + (size_t)bo * 1152 * 16);
    for (int j = t; j < 1152 * 8; j += 256) {
        float2 f = __half22float2(xg[j]);
        int i = j >> 3, q = j & 7;
        float* dst = xs + i * XS_LD + q * 2;
        dst[0] = f.x; dst[1] = f.y;
    }
    const float* cg = g_c + (size_t)bo * 1152;
    for (int i = t; i < 1152; i += 256) cs[i] = cg[i];
    __syncthreads();

    int d = t & 15, g = t >> 4;
    float acc = 0.f;
    for (int i = g; i < 1152; i += 16)
        acc += cs[i] * xs[i * XS_LD + d];
    sred[t] = acc;
    __syncthreads();

    if (t < 16) {
        float s = 0.f;
#pragma unroll
        for (int gg = 0; gg < 16; gg++) s += sred[gg * 16 + t];
        sd[t] = s;
    }
    __syncthreads();

    if (t == 0) {
        float n2 = 0.f;
#pragma unroll
        for (int dd = 0; dd < 16; dd++) n2 += sd[dd] * sd[dd];
        float n = sqrtf(n2);
        float scale = n2 / (1.f + n2) / (n + 1e-8f);
        out[bo] = scale * n;
    }
}

// ---------------- launch ----------------
extern "C" void kernel_launch(void* const* d_in, const int* in_sizes, int n_in,
                              void* d_out, int out_size) {
    const float* x   = (const float*)d_in[0];
    const float* w1  = (const float*)d_in[1];
    const float* b1  = (const float*)d_in[2];
    const float* w2  = (const float*)d_in[3];
    const float* b2  = (const float*)d_in[4];
    const float* cw  = (const float*)d_in[5];
    float* out = (float*)d_out;

    const int CONV2_SMEM = 2 * BUFSZ;                        // 221184 B
    const int ROUTE_SMEM = (1152 * XS_LD + 1152) * 4;        // 96768 B
    const int W2_SMEM    = 256 * 81 * 4;                     // 82944 B
    const int XHAT_SMEM  = 32768 + 4096;                     // 36864 B
    cudaFuncSetAttribute(conv2_mma, cudaFuncAttributeMaxDynamicSharedMemorySize, CONV2_SMEM);
    cudaFuncSetAttribute(convert_w2, cudaFuncAttributeMaxDynamicSharedMemorySize, W2_SMEM);
    cudaFuncSetAttribute(xhat_kernel, cudaFuncAttributeMaxDynamicSharedMemorySize, XHAT_SMEM);
    cudaFuncSetAttribute(routeAB_kernel<0>, cudaFuncAttributeMaxDynamicSharedMemorySize, ROUTE_SMEM);
    cudaFuncSetAttribute(routeAB_kernel<1>, cudaFuncAttributeMaxDynamicSharedMemorySize, ROUTE_SMEM);
    cudaFuncSetAttribute(routeFinal_kernel, cudaFuncAttributeMaxDynamicSharedMemorySize, ROUTE_SMEM);

    float *blog0, *blog1;
    cudaGetSymbolAddress((void**)&blog0, g_blog0);
    cudaGetSymbolAddress((void**)&blog1, g_blog1);

    conv1_kernel<<<dim3(512, 4), 256>>>(x, w1, b1);
    convert_w2<<<256, 256, W2_SMEM>>>(w2);
    conv2_mma<<<dim3(2, 72), 256, CONV2_SMEM>>>(b2);
    xhat_kernel<<<dim3(10, 9, 16), 256, XHAT_SMEM>>>(cw);

    routeAB_kernel<0><<<5120, 256, ROUTE_SMEM>>>(blog0, blog0);   // iter 0: uniform c
    softmax_c<<<(512 * 1152 + 255) / 256, 256>>>(blog0);
    routeAB_kernel<1><<<5120, 256, ROUTE_SMEM>>>(blog0, blog1);   // iter 1
    softmax_c<<<(512 * 1152 + 255) / 256, 256>>>(blog1);
    routeFinal_kernel<<<5120, 256, ROUTE_SMEM>>>(out);            // iter 2: lengths
}

// round 16
// speedup vs baseline: 3.3429x; 1.0166x over previous
#include <cuda_runtime.h>
#include <cuda_bf16.h>
#include <cuda_fp16.h>
#include <math.h>
#include <stdint.h>

// ---------------- scratch (static device globals; no runtime alloc) ----------------
__device__ __nv_bfloat16 g_h1_hi[(size_t)512 * 400 * 256];   // conv1 out hi, [b][pos][ci]
__device__ __nv_bfloat16 g_h1_lo[(size_t)512 * 400 * 256];   // conv1 out lo
__device__ __nv_bfloat16 g_w2_hi[81 * 256 * 256];            // pc_w hi, [kk][co][ci]
__device__ __nv_bfloat16 g_w2_lo[81 * 256 * 256];            // pc_w lo
__device__ float g_h2[512 * 9216];                           // conv2 out [b][i*8+k]
__device__ __half g_xhat[(size_t)512 * 10 * 1152 * 16];      // votes [b][o][i][d] (fp16)
__device__ float g_blog0[512 * 10 * 1152];                   // routing logits ping
__device__ float g_blog1[512 * 10 * 1152];                   // routing logits pong
__device__ float g_c[512 * 10 * 1152];                       // softmax coefficients

#define XS_LD 20   // smem row stride (floats) for x_hat tiles in routing kernels

// ---------------- PTX helpers (sm_80-era; compile on plain sm_103 target) ----------------
__device__ __forceinline__ uint32_t smem_u32(const void* p) {
    uint32_t a;
    asm("{ .reg .u64 t; cvta.to.shared.u64 t, %1; cvt.u32.u64 %0, t; }" : "=r"(a) : "l"(p));
    return a;
}
__device__ __forceinline__ void ldm_x4(uint32_t* r, uint32_t addr) {
    asm volatile("ldmatrix.sync.aligned.m8n8.x4.shared.b16 {%0,%1,%2,%3}, [%4];"
                 : "=r"(r[0]), "=r"(r[1]), "=r"(r[2]), "=r"(r[3]) : "r"(addr));
}
__device__ __forceinline__ void mma_bf16(float* c, const uint32_t* a, const uint32_t* b) {
    asm volatile("mma.sync.aligned.m16n8k16.row.col.f32.bf16.bf16.f32 "
                 "{%0,%1,%2,%3}, {%4,%5,%6,%7}, {%8,%9}, {%0,%1,%2,%3};"
                 : "+f"(c[0]), "+f"(c[1]), "+f"(c[2]), "+f"(c[3])
                 : "r"(a[0]), "r"(a[1]), "r"(a[2]), "r"(a[3]), "r"(b[0]), "r"(b[1]));
}
__device__ __forceinline__ void cp16(uint32_t dst, const void* src) {
    asm volatile("cp.async.cg.shared.global [%0], [%1], 16;" :: "r"(dst), "l"(src));
}
__device__ __forceinline__ void cp_commit() { asm volatile("cp.async.commit_group;" ::: "memory"); }
__device__ __forceinline__ void cp_wait0()  { asm volatile("cp.async.wait_group 0;" ::: "memory"); }

// ---------------- conv1: [512,1,28,28] -> channel-last bf16 hi/lo, ReLU ----------------
__global__ __launch_bounds__(256) void conv1_kernel(const float* __restrict__ x,
                                                    const float* __restrict__ w1,
                                                    const float* __restrict__ b1) {
    __shared__ float xs[784];
    int b  = blockIdx.x;
    int oh0 = blockIdx.y * 5;
    int co = threadIdx.x;
    const float* xb = x + (size_t)b * 784;
    for (int idx = co; idx < 784; idx += 256) xs[idx] = xb[idx];
    __syncthreads();

    float bias = b1[co];
    const float* wco = w1 + co * 81;

    for (int oh = oh0; oh < oh0 + 5; oh++) {
        float acc[20];
#pragma unroll
        for (int ow = 0; ow < 20; ow++) acc[ow] = 0.f;

        for (int kh = 0; kh < 9; kh++) {
            float xr[28];
#pragma unroll
            for (int c = 0; c < 28; c++) xr[c] = xs[(oh + kh) * 28 + c];
#pragma unroll
            for (int kw = 0; kw < 9; kw++) {
                float w = __ldg(&wco[kh * 9 + kw]);
#pragma unroll
                for (int ow = 0; ow < 20; ow++) acc[ow] += w * xr[ow + kw];
            }
        }
        size_t base = (((size_t)b * 400) + oh * 20) * 256 + co;
#pragma unroll
        for (int ow = 0; ow < 20; ow++) {
            float v = acc[ow] + bias;
            v = v > 0.f ? v : 0.f;
            __nv_bfloat16 h = __float2bfloat16(v);
            __nv_bfloat16 l = __float2bfloat16(v - __bfloat162float(h));
            g_h1_hi[base + (size_t)ow * 256] = h;
            g_h1_lo[base + (size_t)ow * 256] = l;
        }
    }
}

// ---------------- pc_w convert (coalesced): [co][ci][k] fp32 -> [kk][co][ci] bf16 hi/lo ----------------
__global__ __launch_bounds__(256) void convert_w2(const float* __restrict__ pcw) {
    extern __shared__ float ws[];    // [ci][81]
    int co = blockIdx.x;
    int t = threadIdx.x;
    const float* src = pcw + (size_t)co * 256 * 81;
    for (int idx = t; idx < 256 * 81; idx += 256) ws[idx] = src[idx];
    __syncthreads();
    int ci = t;
    for (int k = 0; k < 81; k++) {
        float v = ws[ci * 81 + k];
        __nv_bfloat16 h = __float2bfloat16(v);
        __nv_bfloat16 l = __float2bfloat16(v - __bfloat162float(h));
        size_t o = ((size_t)k * 256 + co) * 256 + ci;
        g_w2_hi[o] = h;
        g_w2_lo[o] = l;
    }
}

// ---------------- conv2 via HMMA implicit GEMM, cp.async double-buffered ----------------
#define LDK 72
#define BUFSZ 110592
#define AHI 0
#define ALO 18432
#define BHI 36864
#define BLO 73728
#define NITER 324
__global__ __launch_bounds__(256, 1) void conv2_mma(const float* __restrict__ pcb) {
    extern __shared__ char smem[];
    uint32_t sb = smem_u32(smem);
    int tid = threadIdx.x;
    int wid = tid >> 5;
    int lane = tid & 31;
    int mtile = blockIdx.x;
    int ntile = blockIdx.y;

    int wm = wid & 3;
    int wn = wid >> 2;

    int seg = tid & 7;
    int rbase = tid >> 3;
    uint32_t adst[4];
    uint32_t aoff[4];
#pragma unroll
    for (int j = 0; j < 4; j++) {
        int row = rbase + j * 32;
        adst[j] = (uint32_t)(row * LDK + seg * 8) * 2;
        aoff[j] = (uint32_t)((mtile * 128 + row) * 256 + seg * 8);
    }
    uint32_t bdst[8];
    size_t gb[8];
#pragma unroll
    for (int j = 0; j < 8; j++) {
        int row = rbase + j * 32;
        bdst[j] = (uint32_t)(row * LDK + seg * 8) * 2;
        int p = ntile * 256 + row;
        int b = p / 36;
        int s = p - b * 36;
        int oh = s / 6, ow = s - oh * 6;
        gb[j] = ((size_t)b * 400 + oh * 40 + ow * 2) * 256 + seg * 8;
    }

    float acc[2][16][4];
#pragma unroll
    for (int mt = 0; mt < 2; mt++)
#pragma unroll
        for (int nt = 0; nt < 16; nt++)
#pragma unroll
            for (int j = 0; j < 4; j++) acc[mt][nt][j] = 0.f;

    int rowA = lane & 15;
    int kgA  = (lane >> 4) << 3;
    int rowB = ((lane >> 4) << 3) + (lane & 7);
    int kgB  = ((lane >> 3) & 1) << 3;

#define STAGE(IT, BSEL) do {                                                        \
        int _it = (IT);                                                             \
        int _cb = (_it / 81) << 6;                                                  \
        int _kk = _it - (_it / 81) * 81;                                            \
        int _kh = _kk / 9, _kw = _kk - _kh * 9;                                     \
        uint32_t _bu = sb + (BSEL) * BUFSZ;                                         \
        size_t _abase = ((size_t)_kk * 256) * 256 + _cb;                            \
        size_t _boff = (size_t)(_kh * 20 + _kw) * 256 + _cb;                        \
        _Pragma("unroll")                                                           \
        for (int j = 0; j < 4; j++) {                                               \
            size_t _s = _abase + aoff[j];                                           \
            cp16(_bu + AHI + adst[j], (const char*)g_w2_hi + _s * 2);               \
            cp16(_bu + ALO + adst[j], (const char*)g_w2_lo + _s * 2);               \
        }                                                                           \
        _Pragma("unroll")                                                           \
        for (int j = 0; j < 8; j++) {                                               \
            size_t _s = gb[j] + _boff;                                              \
            cp16(_bu + BHI + bdst[j], (const char*)g_h1_hi + _s * 2);               \
            cp16(_bu + BLO + bdst[j], (const char*)g_h1_lo + _s * 2);               \
        }                                                                           \
    } while (0)

    STAGE(0, 0);
    cp_commit();
    cp_wait0();
    __syncthreads();

    for (int it = 0; it < NITER; it++) {
        if (it + 1 < NITER) { STAGE(it + 1, (it + 1) & 1); cp_commit(); }

        uint32_t bu = sb + (it & 1) * BUFSZ;
#pragma unroll
        for (int ks = 0; ks < 4; ks++) {
            int k0 = ks * 16;
            uint32_t ahi[2][4], alo[2][4];
#pragma unroll
            for (int mt = 0; mt < 2; mt++) {
                uint32_t arow = (uint32_t)((wm * 32 + mt * 16 + rowA) * LDK + k0 + kgA) * 2;
                ldm_x4(ahi[mt], bu + AHI + arow);
                ldm_x4(alo[mt], bu + ALO + arow);
            }
#pragma unroll
            for (int nh = 0; nh < 4; nh++) {
                uint32_t bhi[4][2], blo[4][2];
#pragma unroll
                for (int nq = 0; nq < 2; nq++) {
                    uint32_t brow = (uint32_t)((wn * 128 + nh * 32 + nq * 16 + rowB) * LDK + k0 + kgB) * 2;
                    uint32_t t4[4];
                    ldm_x4(t4, bu + BHI + brow);
                    bhi[2 * nq][0] = t4[0]; bhi[2 * nq][1] = t4[1];
                    bhi[2 * nq + 1][0] = t4[2]; bhi[2 * nq + 1][1] = t4[3];
                    ldm_x4(t4, bu + BLO + brow);
                    blo[2 * nq][0] = t4[0]; blo[2 * nq][1] = t4[1];
                    blo[2 * nq + 1][0] = t4[2]; blo[2 * nq + 1][1] = t4[3];
                }
#pragma unroll
                for (int mt = 0; mt < 2; mt++)
#pragma unroll
                    for (int nq = 0; nq < 4; nq++) {
                        int nt = nh * 4 + nq;
                        mma_bf16(acc[mt][nt], ahi[mt], bhi[nq]);
                        mma_bf16(acc[mt][nt], ahi[mt], blo[nq]);
                        mma_bf16(acc[mt][nt], alo[mt], bhi[nq]);
                    }
            }
        }
        if (it + 1 < NITER) cp_wait0();
        __syncthreads();
    }

    int r0 = lane >> 2, cp = lane & 3;
#pragma unroll
    for (int mt = 0; mt < 2; mt++) {
#pragma unroll
        for (int half = 0; half < 2; half++) {
            int m = wm * 32 + mt * 16 + r0 + half * 8;
            int co = mtile * 128 + m;
            float bias = pcb[co];
#pragma unroll
            for (int nt = 0; nt < 16; nt++) {
#pragma unroll
                for (int e = 0; e < 2; e++) {
                    int p = ntile * 256 + wn * 128 + nt * 8 + 2 * cp + e;
                    int b = p / 36;
                    int s = p - b * 36;
                    g_h2[(size_t)b * 9216 + co * 36 + s] = acc[mt][nt][half * 2 + e] + bias;
                }
            }
        }
    }
}

// ---------------- votes + fused squash: fp16 weights, d-pair threads, LDS.64 weight loads ----------------
__global__ __launch_bounds__(256) void xhat_kernel(const float* __restrict__ cw) {
    extern __shared__ float xsm[];
    __half2* wt = (__half2*)xsm;            // 4 * 2048 half2 = 32768 B
    float* us = xsm + 8192;                 // 1024 floats

    int o  = blockIdx.x;
    int ic = blockIdx.y;
    int bc = blockIdx.z;
    int t  = threadIdx.x;

    const float4* src = (const float4*)(cw + ((size_t)o * 1152 + ic * 128) * 128);
    for (int j = t; j < 4096; j += 256) {
        float4 v = src[j];
        int fo = j * 4;
        int il = fo >> 7, rem = fo & 127;
        int d = rem >> 3, k0 = rem & 7;
        int p0 = k0 >> 1;
        wt[p0 * 2048 + il * 16 + d]       = __floats2half2_rn(v.x, v.y);
        wt[(p0 + 1) * 2048 + il * 16 + d] = __floats2half2_rn(v.z, v.w);
    }
    __syncthreads();

    int d8 = t & 7;
    int tr = t >> 3;

    for (int bl = 0; bl < 32; bl++) {
        int b = bc * 32 + bl;
        const float4* hp = (const float4*)(g_h2 + (size_t)b * 9216 + (size_t)ic * 1024);
        __syncthreads();
        {
            float4 v = hp[t];
            float dp = v.x * v.x + v.y * v.y + v.z * v.z + v.w * v.w;
            float n2 = dp + __shfl_xor_sync(0xffffffffu, dp, 1);
            float n = sqrtf(n2);
            float scale = n2 / (1.f + n2) / (n + 1e-8f);
            v.x *= scale; v.y *= scale; v.z *= scale; v.w *= scale;
            *(float4*)(us + t * 4) = v;
        }
        __syncthreads();

        __half2* xout = (__half2*)(g_xhat + (((size_t)(b * 10 + o) * 1152) + ic * 128) * 16);
#pragma unroll
        for (int isub = 0; isub < 4; isub++) {
            int il = isub * 32 + tr;
            int wi = il * 16 + 2 * d8;
            float4 u0 = *(const float4*)(us + il * 8);
            float4 u1 = *(const float4*)(us + il * 8 + 4);
            float a0 = 0.f, a1 = 0.f;
#pragma unroll
            for (int p = 0; p < 4; p++) {
                uint2 hw = *(const uint2*)(wt + p * 2048 + wi);
                float2 f0 = __half22float2(*(const __half2*)&hw.x);
                float2 f1 = __half22float2(*(const __half2*)&hw.y);
                float uk0 = (p == 0) ? u0.x : (p == 1) ? u0.z : (p == 2) ? u1.x : u1.z;
                float uk1 = (p == 0) ? u0.y : (p == 1) ? u0.w : (p == 2) ? u1.y : u1.w;
                a0 += f0.x * uk0 + f0.y * uk1;
                a1 += f1.x * uk0 + f1.y * uk1;
            }
            xout[il * 8 + d8] = __floats2half2_rn(a0, a1);
        }
    }
}

// ---------------- softmax over output caps ----------------
__global__ __launch_bounds__(256) void softmax_c(const float* __restrict__ blog) {
    int idx = blockIdx.x * 256 + threadIdx.x;
    if (idx >= 512 * 1152) return;
    int b = idx / 1152, i = idx - b * 1152;
    const float* blb = blog + (size_t)b * 10 * 1152 + i;
    float vals[10];
    float m = -1e30f;
#pragma unroll
    for (int o = 0; o < 10; o++) {
        vals[o] = blb[(size_t)o * 1152];
        m = fmaxf(m, vals[o]);
    }
    float sum = 0.f;
#pragma unroll
    for (int o = 0; o < 10; o++) { vals[o] = expf(vals[o] - m); sum += vals[o]; }
    float inv = 1.f / sum;
    float* cb = g_c + (size_t)b * 10 * 1152 + i;
#pragma unroll
    for (int o = 0; o < 10; o++) cb[(size_t)o * 1152] = vals[o] * inv;
}

// ---------------- tile loader: fp16 x_hat -> fp32 smem via LDG.128 ----------------
__device__ __forceinline__ void load_xhat_tile(float* xs, int bo, int t) {
    const uint4* xg = (const uint4*)(g_xhat + (size_t)bo * 1152 * 16);
    for (int j = t; j < 1152 * 2; j += 256) {
        uint4 v = xg[j];                    // 8 halves = half a row
        int i = j >> 1, h = (j & 1) * 8;
        float* dst = xs + i * XS_LD + h;
        float2 f0 = __half22float2(*(const __half2*)&v.x);
        float2 f1 = __half22float2(*(const __half2*)&v.y);
        float2 f2 = __half22float2(*(const __half2*)&v.z);
        float2 f3 = __half22float2(*(const __half2*)&v.w);
        *(float4*)dst       = make_float4(f0.x, f0.y, f1.x, f1.y);
        *(float4*)(dst + 4) = make_float4(f2.x, f2.y, f3.x, f3.y);
    }
}

// ---------------- fused routing A+B (fp16 x_hat, stride-20 smem, float4 passes) ----------------
template <int MODE>
__global__ __launch_bounds__(256) void routeAB_kernel(const float* __restrict__ blin_g,
                                                      float* __restrict__ blout_g) {
    extern __shared__ float sm[];
    float* xs = sm;                    // [1152][XS_LD]
    float* cs = sm + 1152 * XS_LD;     // [1152]
    __shared__ float sred[256];
    __shared__ float sd[16];
    __shared__ float sscale;

    int bo = blockIdx.x;
    int t = threadIdx.x;

    load_xhat_tile(xs, bo, t);

    if (MODE == 1) {
        const float* cg = g_c + (size_t)bo * 1152;
        for (int i = t; i < 1152; i += 256) cs[i] = cg[i];
    } else {
        for (int i = t; i < 1152; i += 256) cs[i] = 0.1f;
    }
    __syncthreads();

    int d = t & 15, g = t >> 4;
    float acc = 0.f;
    for (int i = g; i < 1152; i += 16)
        acc += cs[i] * xs[i * XS_LD + d];
    sred[t] = acc;
    __syncthreads();

    if (t < 16) {
        float s = 0.f;
#pragma unroll
        for (int gg = 0; gg < 16; gg++) s += sred[gg * 16 + t];
        sd[t] = s;
    }
    __syncthreads();

    if (t == 0) {
        float n2 = 0.f;
#pragma unroll
        for (int dd = 0; dd < 16; dd++) n2 += sd[dd] * sd[dd];
        float n = sqrtf(n2);
        sscale = n2 / (1.f + n2) / (n + 1e-8f);
    }
    __syncthreads();

    float scale = sscale;
    float v0 = sd[0], v1 = sd[1], v2 = sd[2], v3 = sd[3];
    float v4 = sd[4], v5 = sd[5], v6 = sd[6], v7 = sd[7];
    float v8 = sd[8], v9 = sd[9], v10 = sd[10], v11 = sd[11];
    float v12 = sd[12], v13 = sd[13], v14 = sd[14], v15 = sd[15];
    const float* blin = blin_g + (size_t)bo * 1152;
    float* blout = blout_g + (size_t)bo * 1152;
    for (int i = t; i < 1152; i += 256) {
        const float* xr = xs + i * XS_LD;
        float4 xa = *(const float4*)(xr);
        float4 xb = *(const float4*)(xr + 4);
        float4 xc = *(const float4*)(xr + 8);
        float4 xd = *(const float4*)(xr + 12);
        float dot = xa.x * v0 + xa.y * v1 + xa.z * v2 + xa.w * v3
                  + xb.x * v4 + xb.y * v5 + xb.z * v6 + xb.w * v7
                  + xc.x * v8 + xc.y * v9 + xc.z * v10 + xc.w * v11
                  + xd.x * v12 + xd.y * v13 + xd.z * v14 + xd.w * v15;
        dot *= scale;
        blout[i] = (MODE == 1) ? (blin[i] + dot) : dot;
    }
}

// ---------------- final routing pass: c -> capsule lengths (fp16 x_hat) ----------------
__global__ __launch_bounds__(256) void routeFinal_kernel(float* __restrict__ out) {
    extern __shared__ float sm[];
    float* xs = sm;                    // [1152][XS_LD]
    float* cs = sm + 1152 * XS_LD;     // [1152]
    __shared__ float sred[256];
    __shared__ float sd[16];

    int bo = blockIdx.x;
    int t = threadIdx.x;

    load_xhat_tile(xs, bo, t);
    const float* cg = g_c + (size_t)bo * 1152;
    for (int i = t; i < 1152; i += 256) cs[i] = cg[i];
    __syncthreads();

    int d = t & 15, g = t >> 4;
    float acc = 0.f;
    for (int i = g; i < 1152; i += 16)
        acc += cs[i] * xs[i * XS_LD + d];
    sred[t] = acc;
    __syncthreads();

    if (t < 16) {
        float s = 0.f;
#pragma unroll
        for (int gg = 0; gg < 16; gg++) s += sred[gg * 16 + t];
        sd[t] = s;
    }
    __syncthreads();

    if (t == 0) {
        float n2 = 0.f;
#pragma unroll
        for (int dd = 0; dd < 16; dd++) n2 += sd[dd] * sd[dd];
        float n = sqrtf(n2);
        float scale = n2 / (1.f + n2) / (n + 1e-8f);
        out[bo] = scale * n;
    }
}

// ---------------- launch ----------------
extern "C" void kernel_launch(void* const* d_in, const int* in_sizes, int n_in,
                              void* d_out, int out_size) {
    const float* x   = (const float*)d_in[0];
    const float* w1  = (const float*)d_in[1];
    const float* b1  = (const float*)d_in[2];
    const float* w2  = (const float*)d_in[3];
    const float* b2  = (const float*)d_in[4];
    const float* cw  = (const float*)d_in[5];
    float* out = (float*)d_out;

    const int CONV2_SMEM = 2 * BUFSZ;                        // 221184 B
    const int ROUTE_SMEM = (1152 * XS_LD + 1152) * 4;        // 96768 B
    const int W2_SMEM    = 256 * 81 * 4;                     // 82944 B
    const int XHAT_SMEM  = 32768 + 4096;                     // 36864 B
    cudaFuncSetAttribute(conv2_mma, cudaFuncAttributeMaxDynamicSharedMemorySize, CONV2_SMEM);
    cudaFuncSetAttribute(convert_w2, cudaFuncAttributeMaxDynamicSharedMemorySize, W2_SMEM);
    cudaFuncSetAttribute(xhat_kernel, cudaFuncAttributeMaxDynamicSharedMemorySize, XHAT_SMEM);
    cudaFuncSetAttribute(routeAB_kernel<0>, cudaFuncAttributeMaxDynamicSharedMemorySize, ROUTE_SMEM);
    cudaFuncSetAttribute(routeAB_kernel<1>, cudaFuncAttributeMaxDynamicSharedMemorySize, ROUTE_SMEM);
    cudaFuncSetAttribute(routeFinal_kernel, cudaFuncAttributeMaxDynamicSharedMemorySize, ROUTE_SMEM);

    float *blog0, *blog1;
    cudaGetSymbolAddress((void**)&blog0, g_blog0);
    cudaGetSymbolAddress((void**)&blog1, g_blog1);

    conv1_kernel<<<dim3(512, 4), 256>>>(x, w1, b1);
    convert_w2<<<256, 256, W2_SMEM>>>(w2);
    conv2_mma<<<dim3(2, 72), 256, CONV2_SMEM>>>(b2);
    xhat_kernel<<<dim3(10, 9, 16), 256, XHAT_SMEM>>>(cw);

    routeAB_kernel<0><<<5120, 256, ROUTE_SMEM>>>(blog0, blog0);   // iter 0: uniform c
    softmax_c<<<(512 * 1152 + 255) / 256, 256>>>(blog0);
    routeAB_kernel<1><<<5120, 256, ROUTE_SMEM>>>(blog0, blog1);   // iter 1
    softmax_c<<<(512 * 1152 + 255) / 256, 256>>>(blog1);
    routeFinal_kernel<<<5120, 256, ROUTE_SMEM>>>(out);            // iter 2: lengths
}

// round 17
// speedup vs baseline: 3.3788x; 1.0107x over previous
#include <cuda_runtime.h>
#include <cuda_bf16.h>
#include <cuda_fp16.h>
#include <math.h>
#include <stdint.h>

// ---------------- scratch (static device globals; no runtime alloc) ----------------
__device__ __nv_bfloat16 g_h1_hi[(size_t)512 * 400 * 256];   // conv1 out hi, [b][pos][ci]
__device__ __nv_bfloat16 g_h1_lo[(size_t)512 * 400 * 256];   // conv1 out lo
__device__ __nv_bfloat16 g_w2_hi[81 * 256 * 256];            // pc_w hi, [kk][co][ci]
__device__ __nv_bfloat16 g_w2_lo[81 * 256 * 256];            // pc_w lo
__device__ float g_h2[512 * 9216];                           // conv2 out [b][i*8+k]
__device__ __half g_xhat[(size_t)512 * 10 * 1152 * 16];      // votes [b][o][i][d] (fp16)
__device__ float g_blog0[512 * 10 * 1152];                   // routing logits ping
__device__ float g_blog1[512 * 10 * 1152];                   // routing logits pong
__device__ float g_c[512 * 10 * 1152];                       // softmax coefficients

#define XS_LD 20   // smem row stride (floats) for x_hat tiles in routing kernels

// ---------------- PTX helpers (sm_80-era; compile on plain sm_103 target) ----------------
__device__ __forceinline__ uint32_t smem_u32(const void* p) {
    uint32_t a;
    asm("{ .reg .u64 t; cvta.to.shared.u64 t, %1; cvt.u32.u64 %0, t; }" : "=r"(a) : "l"(p));
    return a;
}
__device__ __forceinline__ void ldm_x4(uint32_t* r, uint32_t addr) {
    asm volatile("ldmatrix.sync.aligned.m8n8.x4.shared.b16 {%0,%1,%2,%3}, [%4];"
                 : "=r"(r[0]), "=r"(r[1]), "=r"(r[2]), "=r"(r[3]) : "r"(addr));
}
__device__ __forceinline__ void mma_bf16(float* c, const uint32_t* a, const uint32_t* b) {
    asm volatile("mma.sync.aligned.m16n8k16.row.col.f32.bf16.bf16.f32 "
                 "{%0,%1,%2,%3}, {%4,%5,%6,%7}, {%8,%9}, {%0,%1,%2,%3};"
                 : "+f"(c[0]), "+f"(c[1]), "+f"(c[2]), "+f"(c[3])
                 : "r"(a[0]), "r"(a[1]), "r"(a[2]), "r"(a[3]), "r"(b[0]), "r"(b[1]));
}
__device__ __forceinline__ void cp16(uint32_t dst, const void* src) {
    asm volatile("cp.async.cg.shared.global [%0], [%1], 16;" :: "r"(dst), "l"(src));
}
__device__ __forceinline__ void cp_commit() { asm volatile("cp.async.commit_group;" ::: "memory"); }
__device__ __forceinline__ void cp_wait0()  { asm volatile("cp.async.wait_group 0;" ::: "memory"); }

// ---------------- conv1: [512,1,28,28] -> channel-last bf16 hi/lo, ReLU ----------------
__global__ __launch_bounds__(256) void conv1_kernel(const float* __restrict__ x,
                                                    const float* __restrict__ w1,
                                                    const float* __restrict__ b1) {
    __shared__ float xs[784];
    int b  = blockIdx.x;
    int oh0 = blockIdx.y * 5;
    int co = threadIdx.x;
    const float* xb = x + (size_t)b * 784;
    for (int idx = co; idx < 784; idx += 256) xs[idx] = xb[idx];
    __syncthreads();

    float bias = b1[co];
    const float* wco = w1 + co * 81;

    for (int oh = oh0; oh < oh0 + 5; oh++) {
        float acc[20];
#pragma unroll
        for (int ow = 0; ow < 20; ow++) acc[ow] = 0.f;

        for (int kh = 0; kh < 9; kh++) {
            float xr[28];
#pragma unroll
            for (int c = 0; c < 28; c++) xr[c] = xs[(oh + kh) * 28 + c];
#pragma unroll
            for (int kw = 0; kw < 9; kw++) {
                float w = __ldg(&wco[kh * 9 + kw]);
#pragma unroll
                for (int ow = 0; ow < 20; ow++) acc[ow] += w * xr[ow + kw];
            }
        }
        size_t base = (((size_t)b * 400) + oh * 20) * 256 + co;
#pragma unroll
        for (int ow = 0; ow < 20; ow++) {
            float v = acc[ow] + bias;
            v = v > 0.f ? v : 0.f;
            __nv_bfloat16 h = __float2bfloat16(v);
            __nv_bfloat16 l = __float2bfloat16(v - __bfloat162float(h));
            g_h1_hi[base + (size_t)ow * 256] = h;
            g_h1_lo[base + (size_t)ow * 256] = l;
        }
    }
}

// ---------------- pc_w convert (coalesced): [co][ci][k] fp32 -> [kk][co][ci] bf16 hi/lo ----------------
__global__ __launch_bounds__(256) void convert_w2(const float* __restrict__ pcw) {
    extern __shared__ float ws[];    // [ci][81]
    int co = blockIdx.x;
    int t = threadIdx.x;
    const float* src = pcw + (size_t)co * 256 * 81;
    for (int idx = t; idx < 256 * 81; idx += 256) ws[idx] = src[idx];
    __syncthreads();
    int ci = t;
    for (int k = 0; k < 81; k++) {
        float v = ws[ci * 81 + k];
        __nv_bfloat16 h = __float2bfloat16(v);
        __nv_bfloat16 l = __float2bfloat16(v - __bfloat162float(h));
        size_t o = ((size_t)k * 256 + co) * 256 + ci;
        g_w2_hi[o] = h;
        g_w2_lo[o] = l;
    }
}

// ---------------- conv2 via HMMA implicit GEMM, cp.async double-buffered ----------------
#define LDK 72
#define BUFSZ 110592
#define AHI 0
#define ALO 18432
#define BHI 36864
#define BLO 73728
#define NITER 324
__global__ __launch_bounds__(256, 1) void conv2_mma(const float* __restrict__ pcb) {
    extern __shared__ char smem[];
    uint32_t sb = smem_u32(smem);
    int tid = threadIdx.x;
    int wid = tid >> 5;
    int lane = tid & 31;
    int mtile = blockIdx.x;
    int ntile = blockIdx.y;

    int wm = wid & 3;
    int wn = wid >> 2;

    int seg = tid & 7;
    int rbase = tid >> 3;
    uint32_t adst[4];
    uint32_t aoff[4];
#pragma unroll
    for (int j = 0; j < 4; j++) {
        int row = rbase + j * 32;
        adst[j] = (uint32_t)(row * LDK + seg * 8) * 2;
        aoff[j] = (uint32_t)((mtile * 128 + row) * 256 + seg * 8);
    }
    uint32_t bdst[8];
    size_t gb[8];
#pragma unroll
    for (int j = 0; j < 8; j++) {
        int row = rbase + j * 32;
        bdst[j] = (uint32_t)(row * LDK + seg * 8) * 2;
        int p = ntile * 256 + row;
        int b = p / 36;
        int s = p - b * 36;
        int oh = s / 6, ow = s - oh * 6;
        gb[j] = ((size_t)b * 400 + oh * 40 + ow * 2) * 256 + seg * 8;
    }

    float acc[2][16][4];
#pragma unroll
    for (int mt = 0; mt < 2; mt++)
#pragma unroll
        for (int nt = 0; nt < 16; nt++)
#pragma unroll
            for (int j = 0; j < 4; j++) acc[mt][nt][j] = 0.f;

    int rowA = lane & 15;
    int kgA  = (lane >> 4) << 3;
    int rowB = ((lane >> 4) << 3) + (lane & 7);
    int kgB  = ((lane >> 3) & 1) << 3;

#define STAGE(IT, BSEL) do {                                                        \
        int _it = (IT);                                                             \
        int _cb = (_it / 81) << 6;                                                  \
        int _kk = _it - (_it / 81) * 81;                                            \
        int _kh = _kk / 9, _kw = _kk - _kh * 9;                                     \
        uint32_t _bu = sb + (BSEL) * BUFSZ;                                         \
        size_t _abase = ((size_t)_kk * 256) * 256 + _cb;                            \
        size_t _boff = (size_t)(_kh * 20 + _kw) * 256 + _cb;                        \
        _Pragma("unroll")                                                           \
        for (int j = 0; j < 4; j++) {                                               \
            size_t _s = _abase + aoff[j];                                           \
            cp16(_bu + AHI + adst[j], (const char*)g_w2_hi + _s * 2);               \
            cp16(_bu + ALO + adst[j], (const char*)g_w2_lo + _s * 2);               \
        }                                                                           \
        _Pragma("unroll")                                                           \
        for (int j = 0; j < 8; j++) {                                               \
            size_t _s = gb[j] + _boff;                                              \
            cp16(_bu + BHI + bdst[j], (const char*)g_h1_hi + _s * 2);               \
            cp16(_bu + BLO + bdst[j], (const char*)g_h1_lo + _s * 2);               \
        }                                                                           \
    } while (0)

    STAGE(0, 0);
    cp_commit();
    cp_wait0();
    __syncthreads();

    for (int it = 0; it < NITER; it++) {
        if (it + 1 < NITER) { STAGE(it + 1, (it + 1) & 1); cp_commit(); }

        uint32_t bu = sb + (it & 1) * BUFSZ;
#pragma unroll
        for (int ks = 0; ks < 4; ks++) {
            int k0 = ks * 16;
            uint32_t ahi[2][4], alo[2][4];
#pragma unroll
            for (int mt = 0; mt < 2; mt++) {
                uint32_t arow = (uint32_t)((wm * 32 + mt * 16 + rowA) * LDK + k0 + kgA) * 2;
                ldm_x4(ahi[mt], bu + AHI + arow);
                ldm_x4(alo[mt], bu + ALO + arow);
            }
#pragma unroll
            for (int nh = 0; nh < 4; nh++) {
                uint32_t bhi[4][2], blo[4][2];
#pragma unroll
                for (int nq = 0; nq < 2; nq++) {
                    uint32_t brow = (uint32_t)((wn * 128 + nh * 32 + nq * 16 + rowB) * LDK + k0 + kgB) * 2;
                    uint32_t t4[4];
                    ldm_x4(t4, bu + BHI + brow);
                    bhi[2 * nq][0] = t4[0]; bhi[2 * nq][1] = t4[1];
                    bhi[2 * nq + 1][0] = t4[2]; bhi[2 * nq + 1][1] = t4[3];
                    ldm_x4(t4, bu + BLO + brow);
                    blo[2 * nq][0] = t4[0]; blo[2 * nq][1] = t4[1];
                    blo[2 * nq + 1][0] = t4[2]; blo[2 * nq + 1][1] = t4[3];
                }
#pragma unroll
                for (int mt = 0; mt < 2; mt++)
#pragma unroll
                    for (int nq = 0; nq < 4; nq++) {
                        int nt = nh * 4 + nq;
                        mma_bf16(acc[mt][nt], ahi[mt], bhi[nq]);
                        mma_bf16(acc[mt][nt], ahi[mt], blo[nq]);
                        mma_bf16(acc[mt][nt], alo[mt], bhi[nq]);
                    }
            }
        }
        if (it + 1 < NITER) cp_wait0();
        __syncthreads();
    }

    int r0 = lane >> 2, cp = lane & 3;
#pragma unroll
    for (int mt = 0; mt < 2; mt++) {
#pragma unroll
        for (int half = 0; half < 2; half++) {
            int m = wm * 32 + mt * 16 + r0 + half * 8;
            int co = mtile * 128 + m;
            float bias = pcb[co];
#pragma unroll
            for (int nt = 0; nt < 16; nt++) {
#pragma unroll
                for (int e = 0; e < 2; e++) {
                    int p = ntile * 256 + wn * 128 + nt * 8 + 2 * cp + e;
                    int b = p / 36;
                    int s = p - b * 36;
                    g_h2[(size_t)b * 9216 + co * 36 + s] = acc[mt][nt][half * 2 + e] + bias;
                }
            }
        }
    }
}

// ---------------- votes + fused squash: half2 weights + half2 u, HFMA2 accumulate ----------------
__global__ __launch_bounds__(256) void xhat_kernel(const float* __restrict__ cw) {
    extern __shared__ float xsm[];
    __half2* wt = (__half2*)xsm;                 // 4 * 2048 half2 = 32768 B
    __half2* us_h = (__half2*)(xsm + 8192);      // 512 half2 = 2048 B

    int o  = blockIdx.x;
    int ic = blockIdx.y;
    int bc = blockIdx.z;
    int t  = threadIdx.x;

    const float4* src = (const float4*)(cw + ((size_t)o * 1152 + ic * 128) * 128);
    for (int j = t; j < 4096; j += 256) {
        float4 v = src[j];
        int fo = j * 4;
        int il = fo >> 7, rem = fo & 127;
        int d = rem >> 3, k0 = rem & 7;
        int p0 = k0 >> 1;
        wt[p0 * 2048 + il * 16 + d]       = __floats2half2_rn(v.x, v.y);
        wt[(p0 + 1) * 2048 + il * 16 + d] = __floats2half2_rn(v.z, v.w);
    }
    __syncthreads();

    int d8 = t & 7;
    int tr = t >> 3;

    for (int bl = 0; bl < 32; bl++) {
        int b = bc * 32 + bl;
        const float4* hp = (const float4*)(g_h2 + (size_t)b * 9216 + (size_t)ic * 1024);
        __syncthreads();
        {
            float4 v = hp[t];
            float dp = v.x * v.x + v.y * v.y + v.z * v.z + v.w * v.w;
            float n2 = dp + __shfl_xor_sync(0xffffffffu, dp, 1);
            float n = sqrtf(n2);
            float scale = n2 / (1.f + n2) / (n + 1e-8f);
            us_h[2 * t]     = __floats2half2_rn(v.x * scale, v.y * scale);
            us_h[2 * t + 1] = __floats2half2_rn(v.z * scale, v.w * scale);
        }
        __syncthreads();

        __half2* xout = (__half2*)(g_xhat + (((size_t)(b * 10 + o) * 1152) + ic * 128) * 16);
#pragma unroll
        for (int isub = 0; isub < 4; isub++) {
            int il = isub * 32 + tr;
            int wi = il * 16 + 2 * d8;
            // u: 4 half2 k-pairs via 2 LDS.64 (broadcast among d8 threads)
            uint2 uu0 = *(const uint2*)(us_h + il * 4);
            uint2 uu1 = *(const uint2*)(us_h + il * 4 + 2);
            __half2 up[4];
            up[0] = *(const __half2*)&uu0.x; up[1] = *(const __half2*)&uu0.y;
            up[2] = *(const __half2*)&uu1.x; up[3] = *(const __half2*)&uu1.y;
            __half2 acc0 = __floats2half2_rn(0.f, 0.f);
            __half2 acc1 = acc0;
#pragma unroll
            for (int p = 0; p < 4; p++) {
                uint2 hw = *(const uint2*)(wt + p * 2048 + wi);   // LDS.64: (d, d+1)
                acc0 = __hfma2(*(const __half2*)&hw.x, up[p], acc0);
                acc1 = __hfma2(*(const __half2*)&hw.y, up[p], acc1);
            }
            float2 s0 = __half22float2(acc0);
            float2 s1 = __half22float2(acc1);
            xout[il * 8 + d8] = __floats2half2_rn(s0.x + s0.y, s1.x + s1.y);
        }
    }
}

// ---------------- softmax over output caps ----------------
__global__ __launch_bounds__(256) void softmax_c(const float* __restrict__ blog) {
    int idx = blockIdx.x * 256 + threadIdx.x;
    if (idx >= 512 * 1152) return;
    int b = idx / 1152, i = idx - b * 1152;
    const float* blb = blog + (size_t)b * 10 * 1152 + i;
    float vals[10];
    float m = -1e30f;
#pragma unroll
    for (int o = 0; o < 10; o++) {
        vals[o] = blb[(size_t)o * 1152];
        m = fmaxf(m, vals[o]);
    }
    float sum = 0.f;
#pragma unroll
    for (int o = 0; o < 10; o++) { vals[o] = expf(vals[o] - m); sum += vals[o]; }
    float inv = 1.f / sum;
    float* cb = g_c + (size_t)b * 10 * 1152 + i;
#pragma unroll
    for (int o = 0; o < 10; o++) cb[(size_t)o * 1152] = vals[o] * inv;
}

// ---------------- tile loader: fp16 x_hat -> fp32 smem via LDG.128 ----------------
__device__ __forceinline__ void load_xhat_tile(float* xs, int bo, int t) {
    const uint4* xg = (const uint4*)(g_xhat + (size_t)bo * 1152 * 16);
    for (int j = t; j < 1152 * 2; j += 256) {
        uint4 v = xg[j];
        int i = j >> 1, h = (j & 1) * 8;
        float* dst = xs + i * XS_LD + h;
        float2 f0 = __half22float2(*(const __half2*)&v.x);
        float2 f1 = __half22float2(*(const __half2*)&v.y);
        float2 f2 = __half22float2(*(const __half2*)&v.z);
        float2 f3 = __half22float2(*(const __half2*)&v.w);
        *(float4*)dst       = make_float4(f0.x, f0.y, f1.x, f1.y);
        *(float4*)(dst + 4) = make_float4(f2.x, f2.y, f3.x, f3.y);
    }
}

// ---------------- fused routing A+B (vectorized pass-1) ----------------
template <int MODE>
__global__ __launch_bounds__(256) void routeAB_kernel(const float* __restrict__ blin_g,
                                                      float* __restrict__ blout_g) {
    extern __shared__ float sm[];
    float* xs = sm;                    // [1152][XS_LD]
    float* cs = sm + 1152 * XS_LD;     // [1152]
    __shared__ float4 sred4[256];
    __shared__ float sd[16];
    __shared__ float sscale;

    int bo = blockIdx.x;
    int t = threadIdx.x;

    load_xhat_tile(xs, bo, t);

    if (MODE == 1) {
        const float* cg = g_c + (size_t)bo * 1152;
        for (int i = t; i < 1152; i += 256) cs[i] = cg[i];
    } else {
        for (int i = t; i < 1152; i += 256) cs[i] = 0.1f;
    }
    __syncthreads();

    // pass 1: acc4[q] = sum_i c_i * xs[i][4q..4q+3], thread = (q, g)
    int q = t & 3, g = t >> 2;
    float4 acc4 = make_float4(0.f, 0.f, 0.f, 0.f);
    for (int i = g; i < 1152; i += 64) {
        float ci = cs[i];
        float4 xv = *(const float4*)(xs + i * XS_LD + q * 4);
        acc4.x += ci * xv.x; acc4.y += ci * xv.y;
        acc4.z += ci * xv.z; acc4.w += ci * xv.w;
    }
    sred4[t] = acc4;
    __syncthreads();

    if (t < 16) {
        int qq = t >> 2, comp = t & 3;
        float s = 0.f;
        for (int gg = 0; gg < 64; gg++) {
            const float* f = (const float*)&sred4[gg * 4 + qq];
            s += f[comp];
        }
        sd[t] = s;
    }
    __syncthreads();

    if (t == 0) {
        float n2 = 0.f;
#pragma unroll
        for (int dd = 0; dd < 16; dd++) n2 += sd[dd] * sd[dd];
        float n = sqrtf(n2);
        sscale = n2 / (1.f + n2) / (n + 1e-8f);
    }
    __syncthreads();

    float scale = sscale;
    float v0 = sd[0], v1 = sd[1], v2 = sd[2], v3 = sd[3];
    float v4 = sd[4], v5 = sd[5], v6 = sd[6], v7 = sd[7];
    float v8 = sd[8], v9 = sd[9], v10 = sd[10], v11 = sd[11];
    float v12 = sd[12], v13 = sd[13], v14 = sd[14], v15 = sd[15];
    const float* blin = blin_g + (size_t)bo * 1152;
    float* blout = blout_g + (size_t)bo * 1152;
    for (int i = t; i < 1152; i += 256) {
        const float* xr = xs + i * XS_LD;
        float4 xa = *(const float4*)(xr);
        float4 xb = *(const float4*)(xr + 4);
        float4 xc = *(const float4*)(xr + 8);
        float4 xd = *(const float4*)(xr + 12);
        float dot = xa.x * v0 + xa.y * v1 + xa.z * v2 + xa.w * v3
                  + xb.x * v4 + xb.y * v5 + xb.z * v6 + xb.w * v7
                  + xc.x * v8 + xc.y * v9 + xc.z * v10 + xc.w * v11
                  + xd.x * v12 + xd.y * v13 + xd.z * v14 + xd.w * v15;
        dot *= scale;
        blout[i] = (MODE == 1) ? (blin[i] + dot) : dot;
    }
}

// ---------------- final routing pass: c -> capsule lengths (vectorized pass-1) ----------------
__global__ __launch_bounds__(256) void routeFinal_kernel(float* __restrict__ out) {
    extern __shared__ float sm[];
    float* xs = sm;                    // [1152][XS_LD]
    float* cs = sm + 1152 * XS_LD;     // [1152]
    __shared__ float4 sred4[256];
    __shared__ float sd[16];

    int bo = blockIdx.x;
    int t = threadIdx.x;

    load_xhat_tile(xs, bo, t);
    const float* cg = g_c + (size_t)bo * 1152;
    for (int i = t; i < 1152; i += 256) cs[i] = cg[i];
    __syncthreads();

    int q = t & 3, g = t >> 2;
    float4 acc4 = make_float4(0.f, 0.f, 0.f, 0.f);
    for (int i = g; i < 1152; i += 64) {
        float ci = cs[i];
        float4 xv = *(const float4*)(xs + i * XS_LD + q * 4);
        acc4.x += ci * xv.x; acc4.y += ci * xv.y;
        acc4.z += ci * xv.z; acc4.w += ci * xv.w;
    }
    sred4[t] = acc4;
    __syncthreads();

    if (t < 16) {
        int qq = t >> 2, comp = t & 3;
        float s = 0.f;
        for (int gg = 0; gg < 64; gg++) {
            const float* f = (const float*)&sred4[gg * 4 + qq];
            s += f[comp];
        }
        sd[t] = s;
    }
    __syncthreads();

    if (t == 0) {
        float n2 = 0.f;
#pragma unroll
        for (int dd = 0; dd < 16; dd++) n2 += sd[dd] * sd[dd];
        float n = sqrtf(n2);
        float scale = n2 / (1.f + n2) / (n + 1e-8f);
        out[bo] = scale * n;
    }
}

// ---------------- launch ----------------
extern "C" void kernel_launch(void* const* d_in, const int* in_sizes, int n_in,
                              void* d_out, int out_size) {
    const float* x   = (const float*)d_in[0];
    const float* w1  = (const float*)d_in[1];
    const float* b1  = (const float*)d_in[2];
    const float* w2  = (const float*)d_in[3];
    const float* b2  = (const float*)d_in[4];
    const float* cw  = (const float*)d_in[5];
    float* out = (float*)d_out;

    const int CONV2_SMEM = 2 * BUFSZ;                        // 221184 B
    const int ROUTE_SMEM = (1152 * XS_LD + 1152) * 4;        // 96768 B
    const int W2_SMEM    = 256 * 81 * 4;                     // 82944 B
    const int XHAT_SMEM  = 32768 + 2048;                     // 34816 B
    cudaFuncSetAttribute(conv2_mma, cudaFuncAttributeMaxDynamicSharedMemorySize, CONV2_SMEM);
    cudaFuncSetAttribute(convert_w2, cudaFuncAttributeMaxDynamicSharedMemorySize, W2_SMEM);
    cudaFuncSetAttribute(xhat_kernel, cudaFuncAttributeMaxDynamicSharedMemorySize, XHAT_SMEM);
    cudaFuncSetAttribute(routeAB_kernel<0>, cudaFuncAttributeMaxDynamicSharedMemorySize, ROUTE_SMEM);
    cudaFuncSetAttribute(routeAB_kernel<1>, cudaFuncAttributeMaxDynamicSharedMemorySize, ROUTE_SMEM);
    cudaFuncSetAttribute(routeFinal_kernel, cudaFuncAttributeMaxDynamicSharedMemorySize, ROUTE_SMEM);

    float *blog0, *blog1;
    cudaGetSymbolAddress((void**)&blog0, g_blog0);
    cudaGetSymbolAddress((void**)&blog1, g_blog1);

    conv1_kernel<<<dim3(512, 4), 256>>>(x, w1, b1);
    convert_w2<<<256, 256, W2_SMEM>>>(w2);
    conv2_mma<<<dim3(2, 72), 256, CONV2_SMEM>>>(b2);
    xhat_kernel<<<dim3(10, 9, 16), 256, XHAT_SMEM>>>(cw);

    routeAB_kernel<0><<<5120, 256, ROUTE_SMEM>>>(blog0, blog0);   // iter 0: uniform c
    softmax_c<<<(512 * 1152 + 255) / 256, 256>>>(blog0);
    routeAB_kernel<1><<<5120, 256, ROUTE_SMEM>>>(blog0, blog1);   // iter 1
    softmax_c<<<(512 * 1152 + 255) / 256, 256>>>(blog1);
    routeFinal_kernel<<<5120, 256, ROUTE_SMEM>>>(out);            // iter 2: lengths
}